// round 1
// baseline (speedup 1.0000x reference)
#include <cuda_runtime.h>
#include <math.h>

#define BCNT  4
#define SEQ   1024
#define EMB   512
#define NH    8
#define HD    64
#define MROWS 4096
#define TMAXS 20

// scratch (static device globals; allocation-free per harness rules)
__device__ float g_q[MROWS * EMB];
__device__ float g_k[MROWS * EMB];
__device__ float g_v[MROWS * EMB];
__device__ float g_attn[MROWS * EMB];
__device__ int   g_T[MROWS];

// ---------------------------------------------------------------------------
// Kernel A: gate + complexity MLPs -> adaptive window T_i per (b,s) row.
// 1 block = 8 rows, 128 threads.
// ---------------------------------------------------------------------------
__global__ __launch_bounds__(128) void gate_kernel(
    const float* __restrict__ x,
    const float* __restrict__ gW1, const float* __restrict__ gb1,
    const float* __restrict__ gg,  const float* __restrict__ gbe,
    const float* __restrict__ gW2, const float* __restrict__ gb2,
    const float* __restrict__ gW3, const float* __restrict__ gb3,
    const float* __restrict__ cW1, const float* __restrict__ cb1,
    const float* __restrict__ cg,  const float* __restrict__ cbe,
    const float* __restrict__ cW2, const float* __restrict__ cb2,
    const float* __restrict__ cW3, const float* __restrict__ cb3)
{
    __shared__ float xs[8][EMB];
    __shared__ float h1[8][128];
    __shared__ float h2[8][64];
    __shared__ float h1c[8][64];
    __shared__ float h2c[8][32];
    __shared__ float stat[8][2];
    __shared__ float gsc[8], csc[8];

    const int tid  = threadIdx.x;
    const int wid  = tid >> 5, lane = tid & 31;
    const int row0 = blockIdx.x * 8;

    for (int i = tid; i < 8 * EMB; i += 128)
        xs[i >> 9][i & 511] = x[row0 * EMB + i];
    __syncthreads();

    // ---- gate path: 512 -> 128 ----
    {
        float acc[8];
        float bv = gb1[tid];
        #pragma unroll
        for (int r = 0; r < 8; r++) acc[r] = bv;
        for (int e = 0; e < EMB; e++) {
            float w = gW1[e * 128 + tid];
            #pragma unroll
            for (int r = 0; r < 8; r++) acc[r] = fmaf(xs[r][e], w, acc[r]);
        }
        #pragma unroll
        for (int r = 0; r < 8; r++) h1[r][tid] = acc[r];
    }
    __syncthreads();
    // LN stats over 128 features; warp handles 2 rows
    for (int r = wid * 2; r < wid * 2 + 2; r++) {
        float v0 = h1[r][lane], v1 = h1[r][lane + 32], v2 = h1[r][lane + 64], v3 = h1[r][lane + 96];
        float s = v0 + v1 + v2 + v3;
        float ss = v0 * v0 + v1 * v1 + v2 * v2 + v3 * v3;
        #pragma unroll
        for (int o = 16; o >= 1; o >>= 1) {
            s  += __shfl_xor_sync(0xffffffffu, s, o);
            ss += __shfl_xor_sync(0xffffffffu, ss, o);
        }
        if (lane == 0) {
            float mu = s / 128.f;
            stat[r][0] = mu;
            stat[r][1] = ss / 128.f - mu * mu;
        }
    }
    __syncthreads();
    #pragma unroll
    for (int r = 0; r < 8; r++) {
        float mu = stat[r][0], var = stat[r][1];
        float v = (h1[r][tid] - mu) * rsqrtf(var + 1e-5f) * gg[tid] + gbe[tid];
        h1[r][tid] = fmaxf(v, 0.f);
    }
    __syncthreads();
    // 128 -> 64
    {
        int j = tid & 63, rr = tid >> 6;
        for (int rp = 0; rp < 4; rp++) {
            int r = rp * 2 + rr;
            float a = gb2[j];
            for (int i = 0; i < 128; i++) a = fmaf(h1[r][i], gW2[i * 64 + j], a);
            h2[r][j] = fmaxf(a, 0.f);
        }
    }
    __syncthreads();
    // 64 -> 1, sigmoid
    for (int r = wid * 2; r < wid * 2 + 2; r++) {
        float a = h2[r][lane] * gW3[lane] + h2[r][lane + 32] * gW3[lane + 32];
        #pragma unroll
        for (int o = 16; o >= 1; o >>= 1) a += __shfl_xor_sync(0xffffffffu, a, o);
        if (lane == 0) gsc[r] = 1.f / (1.f + expf(-(a + gb3[0])));
    }
    __syncthreads();

    // ---- complexity path: 512 -> 64 ----
    if (tid < 64) {
        float acc[8];
        float bv = cb1[tid];
        #pragma unroll
        for (int r = 0; r < 8; r++) acc[r] = bv;
        for (int e = 0; e < EMB; e++) {
            float w = cW1[e * 64 + tid];
            #pragma unroll
            for (int r = 0; r < 8; r++) acc[r] = fmaf(xs[r][e], w, acc[r]);
        }
        #pragma unroll
        for (int r = 0; r < 8; r++) h1c[r][tid] = acc[r];
    }
    __syncthreads();
    for (int r = wid * 2; r < wid * 2 + 2; r++) {
        float v0 = h1c[r][lane], v1 = h1c[r][lane + 32];
        float s = v0 + v1;
        float ss = v0 * v0 + v1 * v1;
        #pragma unroll
        for (int o = 16; o >= 1; o >>= 1) {
            s  += __shfl_xor_sync(0xffffffffu, s, o);
            ss += __shfl_xor_sync(0xffffffffu, ss, o);
        }
        if (lane == 0) {
            float mu = s / 64.f;
            stat[r][0] = mu;
            stat[r][1] = ss / 64.f - mu * mu;
        }
    }
    __syncthreads();
    if (tid < 64) {
        #pragma unroll
        for (int r = 0; r < 8; r++) {
            float mu = stat[r][0], var = stat[r][1];
            float v = (h1c[r][tid] - mu) * rsqrtf(var + 1e-5f) * cg[tid] + cbe[tid];
            h1c[r][tid] = fmaxf(v, 0.f);
        }
    }
    __syncthreads();
    // 64 -> 32
    {
        int j = tid & 31, rr = tid >> 5;
        for (int rp = 0; rp < 2; rp++) {
            int r = rp * 4 + rr;
            float a = cb2[j];
            for (int i = 0; i < 64; i++) a = fmaf(h1c[r][i], cW2[i * 32 + j], a);
            h2c[r][j] = fmaxf(a, 0.f);
        }
    }
    __syncthreads();
    for (int r = wid * 2; r < wid * 2 + 2; r++) {
        float a = h2c[r][lane] * cW3[lane];
        #pragma unroll
        for (int o = 16; o >= 1; o >>= 1) a += __shfl_xor_sync(0xffffffffu, a, o);
        if (lane == 0) csc[r] = 1.f / (1.f + expf(-(a + cb3[0])));
    }
    __syncthreads();

    if (tid < 8) {
        int srow = (row0 + tid) & (SEQ - 1);
        float pos = 0.8f + 0.4f * (float)srow / 1023.f;
        float score = (0.7f * gsc[tid] + 0.3f * csc[tid]) * pos;
        int T = (int)ceilf(score * 20.f);
        T = min(max(T, 1), TMAXS);
        g_T[row0 + tid] = T;
    }
}

// ---------------------------------------------------------------------------
// Kernel B: fused QKV GEMM (128x128x8 tiled fp32) + LIF spike-sum epilogue.
// blockIdx.z selects {Wq, Wk, Wv}. Writes g_q / g_k / g_v (v divided by 20).
// ---------------------------------------------------------------------------
__global__ __launch_bounds__(256) void qkv_kernel(
    const float* __restrict__ x,
    const float* __restrict__ Wq, const float* __restrict__ Wk, const float* __restrict__ Wv,
    const float* __restrict__ aq, const float* __restrict__ bq,
    const float* __restrict__ ak, const float* __restrict__ bk,
    const float* __restrict__ av, const float* __restrict__ bv)
{
    const int z = blockIdx.z;
    const float* W = (z == 0) ? Wq : ((z == 1) ? Wk : Wv);
    float* out = (z == 0) ? g_q : ((z == 1) ? g_k : g_v);
    const float alpha = ((z == 0) ? aq : ((z == 1) ? ak : av))[0];
    const float beta  = ((z == 0) ? bq : ((z == 1) ? bk : bv))[0];
    const float vscale = (z == 2) ? (1.f / 20.f) : 1.f;

    __shared__ float As[8][128];
    __shared__ float Bs[8][128];
    const int t = threadIdx.x;
    const int tx = t & 15, ty = t >> 4;
    const int bm = blockIdx.y * 128, bn = blockIdx.x * 128;
    const int arow = t >> 1, akq = (t & 1) * 4;
    const int brow = t >> 5, bcol = (t & 31) * 4;

    float c[8][8];
    #pragma unroll
    for (int i = 0; i < 8; i++)
        #pragma unroll
        for (int j = 0; j < 8; j++) c[i][j] = 0.f;

    for (int k0 = 0; k0 < EMB; k0 += 8) {
        float4 a4 = *(const float4*)(x + (size_t)(bm + arow) * EMB + k0 + akq);
        float4 b4 = *(const float4*)(W + (size_t)(k0 + brow) * EMB + bn + bcol);
        __syncthreads();
        As[akq + 0][arow] = a4.x;
        As[akq + 1][arow] = a4.y;
        As[akq + 2][arow] = a4.z;
        As[akq + 3][arow] = a4.w;
        *(float4*)&Bs[brow][bcol] = b4;
        __syncthreads();
        #pragma unroll
        for (int k = 0; k < 8; k++) {
            float a[8], b[8];
            *(float4*)(a)     = *(float4*)&As[k][ty * 4];
            *(float4*)(a + 4) = *(float4*)&As[k][64 + ty * 4];
            *(float4*)(b)     = *(float4*)&Bs[k][tx * 4];
            *(float4*)(b + 4) = *(float4*)&Bs[k][64 + tx * 4];
            #pragma unroll
            for (int i = 0; i < 8; i++)
                #pragma unroll
                for (int j = 0; j < 8; j++)
                    c[i][j] = fmaf(a[i], b[j], c[i][j]);
        }
    }

    // LIF epilogue: exact — dynamics at t >= T_i never contribute to acc.
    #pragma unroll
    for (int i = 0; i < 8; i++) {
        const int r = bm + ((i < 4) ? (ty * 4 + i) : (64 + ty * 4 + (i - 4)));
        const int T = g_T[r];
        float iv[8], vv[8], acc[8];
        #pragma unroll
        for (int j = 0; j < 8; j++) { iv[j] = 0.f; vv[j] = 0.f; acc[j] = 0.f; }
        for (int tt = 0; tt < T; tt++) {
            #pragma unroll
            for (int j = 0; j < 8; j++) {
                iv[j] = fmaf(alpha, iv[j], c[i][j]);
                vv[j] = fmaf(beta, vv[j], iv[j]);
                float sp = (vv[j] >= 1.f) ? 1.f : 0.f;
                acc[j] += sp;
                vv[j] *= (1.f - sp);
            }
        }
        float4 r0 = make_float4(acc[0] * vscale, acc[1] * vscale, acc[2] * vscale, acc[3] * vscale);
        float4 r1 = make_float4(acc[4] * vscale, acc[5] * vscale, acc[6] * vscale, acc[7] * vscale);
        *(float4*)(out + (size_t)r * EMB + bn + tx * 4)      = r0;
        *(float4*)(out + (size_t)r * EMB + bn + 64 + tx * 4) = r1;
    }
}

// ---------------------------------------------------------------------------
// Kernel C: flash attention, fp32. 1 CTA = (b, h, 128 q rows), chunks of 64 keys.
// Dynamic smem: Qs[64][132] (d-major), Ks[64][68] (d-major), Vs[64][68], Ps[128][68].
// ---------------------------------------------------------------------------
#define ATTN_SMEM_FLOATS (64 * 132 + 64 * 68 + 64 * 68 + 128 * 68)

__global__ __launch_bounds__(256) void attn_kernel()
{
    extern __shared__ float sm[];
    float* Qs = sm;                    // [64][132]  Qs[d][r]
    float* Ks = Qs + 64 * 132;         // [64][68]   Ks[d][j]
    float* Vs = Ks + 64 * 68;          // [64][68]   Vs[j][d]
    float* Ps = Vs + 64 * 68;          // [128][68]  Ps[r][j]

    const int b = blockIdx.z, h = blockIdx.y;
    const int q0 = blockIdx.x * 128;
    const int t = threadIdx.x, tx = t & 15, ty = t >> 4;

    const float* Qg = g_q + (size_t)(b * SEQ + q0) * EMB + h * HD;
    const float* Kg = g_k + (size_t)(b * SEQ) * EMB + h * HD;
    const float* Vg = g_v + (size_t)(b * SEQ) * EMB + h * HD;

    // load Q tile transposed [d][r]
    #pragma unroll
    for (int it = 0; it < 8; it++) {
        int idx = it * 256 + t;
        int r = idx >> 4, dq = idx & 15;
        float4 q4 = *(const float4*)(Qg + (size_t)r * EMB + dq * 4);
        Qs[(dq * 4 + 0) * 132 + r] = q4.x;
        Qs[(dq * 4 + 1) * 132 + r] = q4.y;
        Qs[(dq * 4 + 2) * 132 + r] = q4.z;
        Qs[(dq * 4 + 3) * 132 + r] = q4.w;
    }

    float m_[8], l_[8], o_[8][4];
    #pragma unroll
    for (int i = 0; i < 8; i++) {
        m_[i] = -1e30f; l_[i] = 0.f;
        #pragma unroll
        for (int j = 0; j < 4; j++) o_[i][j] = 0.f;
    }

    for (int j0 = 0; j0 < SEQ; j0 += 64) {
        __syncthreads();  // Q load / previous PV complete
        #pragma unroll
        for (int it = 0; it < 4; it++) {
            int idx = it * 256 + t;
            int j = idx >> 4, dq = idx & 15;
            float4 k4 = *(const float4*)(Kg + (size_t)(j0 + j) * EMB + dq * 4);
            Ks[(dq * 4 + 0) * 68 + j] = k4.x;
            Ks[(dq * 4 + 1) * 68 + j] = k4.y;
            Ks[(dq * 4 + 2) * 68 + j] = k4.z;
            Ks[(dq * 4 + 3) * 68 + j] = k4.w;
            float4 v4 = *(const float4*)(Vg + (size_t)(j0 + j) * EMB + dq * 4);
            *(float4*)&Vs[j * 68 + dq * 4] = v4;
        }
        __syncthreads();

        // scores S = Q @ K^T  -> s[8][4]
        float s[8][4];
        #pragma unroll
        for (int i = 0; i < 8; i++)
            #pragma unroll
            for (int j = 0; j < 4; j++) s[i][j] = 0.f;
        #pragma unroll 16
        for (int d = 0; d < 64; d++) {
            float a[8], bb[4];
            *(float4*)(a)     = *(float4*)&Qs[d * 132 + ty * 4];
            *(float4*)(a + 4) = *(float4*)&Qs[d * 132 + 64 + ty * 4];
            *(float4*)(bb)    = *(float4*)&Ks[d * 68 + tx * 4];
            #pragma unroll
            for (int i = 0; i < 8; i++)
                #pragma unroll
                for (int j = 0; j < 4; j++)
                    s[i][j] = fmaf(a[i], bb[j], s[i][j]);
        }

        // online softmax (row stats across the 16 tx lanes sharing ty)
        #pragma unroll
        for (int i = 0; i < 8; i++) {
            float mx = -1e30f;
            #pragma unroll
            for (int j = 0; j < 4; j++) {
                s[i][j] *= 0.125f;  // D^-0.5
                mx = fmaxf(mx, s[i][j]);
            }
            #pragma unroll
            for (int o = 8; o >= 1; o >>= 1)
                mx = fmaxf(mx, __shfl_xor_sync(0xffffffffu, mx, o));
            float mn = fmaxf(m_[i], mx);
            float fac = __expf(m_[i] - mn);
            float sum = 0.f;
            #pragma unroll
            for (int j = 0; j < 4; j++) {
                float p = __expf(s[i][j] - mn);
                s[i][j] = p;
                sum += p;
            }
            #pragma unroll
            for (int o = 8; o >= 1; o >>= 1)
                sum += __shfl_xor_sync(0xffffffffu, sum, o);
            l_[i] = l_[i] * fac + sum;
            m_[i] = mn;
            #pragma unroll
            for (int j = 0; j < 4; j++) o_[i][j] *= fac;
        }

        // stage P
        #pragma unroll
        for (int i = 0; i < 8; i++) {
            int r = (i < 4) ? (ty * 4 + i) : (64 + ty * 4 + (i - 4));
            *(float4*)&Ps[r * 68 + tx * 4] = make_float4(s[i][0], s[i][1], s[i][2], s[i][3]);
        }
        __syncthreads();

        // O += P @ V
        #pragma unroll 8
        for (int j = 0; j < 64; j++) {
            float bb[4];
            *(float4*)bb = *(float4*)&Vs[j * 68 + tx * 4];
            #pragma unroll
            for (int i = 0; i < 8; i++) {
                int r = (i < 4) ? (ty * 4 + i) : (64 + ty * 4 + (i - 4));
                float a = Ps[r * 68 + j];
                o_[i][0] = fmaf(a, bb[0], o_[i][0]);
                o_[i][1] = fmaf(a, bb[1], o_[i][1]);
                o_[i][2] = fmaf(a, bb[2], o_[i][2]);
                o_[i][3] = fmaf(a, bb[3], o_[i][3]);
            }
        }
    }

    float* Og = g_attn + (size_t)(b * SEQ + q0) * EMB + h * HD;
    #pragma unroll
    for (int i = 0; i < 8; i++) {
        int r = (i < 4) ? (ty * 4 + i) : (64 + ty * 4 + (i - 4));
        float rl = 1.f / l_[i];
        *(float4*)(Og + (size_t)r * EMB + tx * 4) =
            make_float4(o_[i][0] * rl, o_[i][1] * rl, o_[i][2] * rl, o_[i][3] * rl);
    }
}

// ---------------------------------------------------------------------------
// Kernel D: output projection  out = g_attn @ Wo + bo
// ---------------------------------------------------------------------------
__global__ __launch_bounds__(256) void proj_kernel(
    const float* __restrict__ Wo, const float* __restrict__ bo, float* __restrict__ out)
{
    __shared__ float As[8][128];
    __shared__ float Bs[8][128];
    const int t = threadIdx.x;
    const int tx = t & 15, ty = t >> 4;
    const int bm = blockIdx.y * 128, bn = blockIdx.x * 128;
    const int arow = t >> 1, akq = (t & 1) * 4;
    const int brow = t >> 5, bcol = (t & 31) * 4;

    float c[8][8];
    #pragma unroll
    for (int i = 0; i < 8; i++)
        #pragma unroll
        for (int j = 0; j < 8; j++) c[i][j] = 0.f;

    for (int k0 = 0; k0 < EMB; k0 += 8) {
        float4 a4 = *(const float4*)(g_attn + (size_t)(bm + arow) * EMB + k0 + akq);
        float4 b4 = *(const float4*)(Wo + (size_t)(k0 + brow) * EMB + bn + bcol);
        __syncthreads();
        As[akq + 0][arow] = a4.x;
        As[akq + 1][arow] = a4.y;
        As[akq + 2][arow] = a4.z;
        As[akq + 3][arow] = a4.w;
        *(float4*)&Bs[brow][bcol] = b4;
        __syncthreads();
        #pragma unroll
        for (int k = 0; k < 8; k++) {
            float a[8], b[8];
            *(float4*)(a)     = *(float4*)&As[k][ty * 4];
            *(float4*)(a + 4) = *(float4*)&As[k][64 + ty * 4];
            *(float4*)(b)     = *(float4*)&Bs[k][tx * 4];
            *(float4*)(b + 4) = *(float4*)&Bs[k][64 + tx * 4];
            #pragma unroll
            for (int i = 0; i < 8; i++)
                #pragma unroll
                for (int j = 0; j < 8; j++)
                    c[i][j] = fmaf(a[i], b[j], c[i][j]);
        }
    }

    float4 bo0 = *(const float4*)(bo + bn + tx * 4);
    float4 bo1 = *(const float4*)(bo + bn + 64 + tx * 4);
    #pragma unroll
    for (int i = 0; i < 8; i++) {
        int r = bm + ((i < 4) ? (ty * 4 + i) : (64 + ty * 4 + (i - 4)));
        float4 r0 = make_float4(c[i][0] + bo0.x, c[i][1] + bo0.y, c[i][2] + bo0.z, c[i][3] + bo0.w);
        float4 r1 = make_float4(c[i][4] + bo1.x, c[i][5] + bo1.y, c[i][6] + bo1.z, c[i][7] + bo1.w);
        *(float4*)(out + (size_t)r * EMB + bn + tx * 4)      = r0;
        *(float4*)(out + (size_t)r * EMB + bn + 64 + tx * 4) = r1;
    }
}

// ---------------------------------------------------------------------------
extern "C" void kernel_launch(void* const* d_in, const int* in_sizes, int n_in,
                              void* d_out, int out_size)
{
    (void)in_sizes; (void)n_in; (void)out_size;
    const float* x   = (const float*)d_in[0];
    const float* Wq  = (const float*)d_in[1];
    const float* Wk  = (const float*)d_in[2];
    const float* Wv  = (const float*)d_in[3];
    const float* Wo  = (const float*)d_in[4];
    const float* bo  = (const float*)d_in[5];
    const float* gW1 = (const float*)d_in[6];
    const float* gb1 = (const float*)d_in[7];
    const float* gg  = (const float*)d_in[8];
    const float* gbe = (const float*)d_in[9];
    const float* gW2 = (const float*)d_in[10];
    const float* gb2 = (const float*)d_in[11];
    const float* gW3 = (const float*)d_in[12];
    const float* gb3 = (const float*)d_in[13];
    const float* cW1 = (const float*)d_in[14];
    const float* cb1 = (const float*)d_in[15];
    const float* cg  = (const float*)d_in[16];
    const float* cbe = (const float*)d_in[17];
    const float* cW2 = (const float*)d_in[18];
    const float* cb2 = (const float*)d_in[19];
    const float* cW3 = (const float*)d_in[20];
    const float* cb3 = (const float*)d_in[21];
    const float* aq  = (const float*)d_in[22];
    const float* bq  = (const float*)d_in[23];
    const float* ak  = (const float*)d_in[24];
    const float* bk  = (const float*)d_in[25];
    const float* av  = (const float*)d_in[26];
    const float* bv  = (const float*)d_in[27];
    float* out = (float*)d_out;

    const int attn_smem = ATTN_SMEM_FLOATS * (int)sizeof(float);  // 103424 B
    cudaFuncSetAttribute((const void*)attn_kernel,
                         cudaFuncAttributeMaxDynamicSharedMemorySize, attn_smem);

    gate_kernel<<<MROWS / 8, 128>>>(x, gW1, gb1, gg, gbe, gW2, gb2, gW3, gb3,
                                    cW1, cb1, cg, cbe, cW2, cb2, cW3, cb3);

    qkv_kernel<<<dim3(EMB / 128, MROWS / 128, 3), 256>>>(x, Wq, Wk, Wv,
                                                         aq, bq, ak, bk, av, bv);

    attn_kernel<<<dim3(SEQ / 128, NH, BCNT), 256, attn_smem>>>();

    proj_kernel<<<dim3(EMB / 128, MROWS / 128), 256>>>(Wo, bo, out);
}

// round 2
// speedup vs baseline: 1.0248x; 1.0248x over previous
#include <cuda_runtime.h>
#include <math.h>

#define BCNT  4
#define SEQ   1024
#define EMB   512
#define NH    8
#define HD    64
#define MROWS 4096
#define TMAXS 20

// scratch (static device globals; allocation-free per harness rules)
__device__ float g_q[MROWS * EMB];
__device__ float g_k[MROWS * EMB];
__device__ float g_v[MROWS * EMB];
__device__ float g_attn[MROWS * EMB];
__device__ int   g_T[MROWS];

// ---------------------------------------------------------------------------
// Kernel A: gate + complexity MLPs -> adaptive window T_i per (b,s) row.
// 1 block = 8 rows, 128 threads.
// ---------------------------------------------------------------------------
__global__ __launch_bounds__(128) void gate_kernel(
    const float* __restrict__ x,
    const float* __restrict__ gW1, const float* __restrict__ gb1,
    const float* __restrict__ gg,  const float* __restrict__ gbe,
    const float* __restrict__ gW2, const float* __restrict__ gb2,
    const float* __restrict__ gW3, const float* __restrict__ gb3,
    const float* __restrict__ cW1, const float* __restrict__ cb1,
    const float* __restrict__ cg,  const float* __restrict__ cbe,
    const float* __restrict__ cW2, const float* __restrict__ cb2,
    const float* __restrict__ cW3, const float* __restrict__ cb3)
{
    __shared__ float xs[8][EMB];
    __shared__ float h1[8][128];
    __shared__ float h2[8][64];
    __shared__ float h1c[8][64];
    __shared__ float h2c[8][32];
    __shared__ float stat[8][2];
    __shared__ float gsc[8], csc[8];

    const int tid  = threadIdx.x;
    const int wid  = tid >> 5, lane = tid & 31;
    const int row0 = blockIdx.x * 8;

    for (int i = tid; i < 8 * EMB; i += 128)
        xs[i >> 9][i & 511] = x[row0 * EMB + i];
    __syncthreads();

    // ---- gate path: 512 -> 128 ----
    {
        float acc[8];
        float bv = gb1[tid];
        #pragma unroll
        for (int r = 0; r < 8; r++) acc[r] = bv;
        for (int e = 0; e < EMB; e++) {
            float w = gW1[e * 128 + tid];
            #pragma unroll
            for (int r = 0; r < 8; r++) acc[r] = fmaf(xs[r][e], w, acc[r]);
        }
        #pragma unroll
        for (int r = 0; r < 8; r++) h1[r][tid] = acc[r];
    }
    __syncthreads();
    for (int r = wid * 2; r < wid * 2 + 2; r++) {
        float v0 = h1[r][lane], v1 = h1[r][lane + 32], v2 = h1[r][lane + 64], v3 = h1[r][lane + 96];
        float s = v0 + v1 + v2 + v3;
        float ss = v0 * v0 + v1 * v1 + v2 * v2 + v3 * v3;
        #pragma unroll
        for (int o = 16; o >= 1; o >>= 1) {
            s  += __shfl_xor_sync(0xffffffffu, s, o);
            ss += __shfl_xor_sync(0xffffffffu, ss, o);
        }
        if (lane == 0) {
            float mu = s / 128.f;
            stat[r][0] = mu;
            stat[r][1] = ss / 128.f - mu * mu;
        }
    }
    __syncthreads();
    #pragma unroll
    for (int r = 0; r < 8; r++) {
        float mu = stat[r][0], var = stat[r][1];
        float v = (h1[r][tid] - mu) * rsqrtf(var + 1e-5f) * gg[tid] + gbe[tid];
        h1[r][tid] = fmaxf(v, 0.f);
    }
    __syncthreads();
    {
        int j = tid & 63, rr = tid >> 6;
        for (int rp = 0; rp < 4; rp++) {
            int r = rp * 2 + rr;
            float a = gb2[j];
            for (int i = 0; i < 128; i++) a = fmaf(h1[r][i], gW2[i * 64 + j], a);
            h2[r][j] = fmaxf(a, 0.f);
        }
    }
    __syncthreads();
    for (int r = wid * 2; r < wid * 2 + 2; r++) {
        float a = h2[r][lane] * gW3[lane] + h2[r][lane + 32] * gW3[lane + 32];
        #pragma unroll
        for (int o = 16; o >= 1; o >>= 1) a += __shfl_xor_sync(0xffffffffu, a, o);
        if (lane == 0) gsc[r] = 1.f / (1.f + expf(-(a + gb3[0])));
    }
    __syncthreads();

    // ---- complexity path: 512 -> 64 ----
    if (tid < 64) {
        float acc[8];
        float bv = cb1[tid];
        #pragma unroll
        for (int r = 0; r < 8; r++) acc[r] = bv;
        for (int e = 0; e < EMB; e++) {
            float w = cW1[e * 64 + tid];
            #pragma unroll
            for (int r = 0; r < 8; r++) acc[r] = fmaf(xs[r][e], w, acc[r]);
        }
        #pragma unroll
        for (int r = 0; r < 8; r++) h1c[r][tid] = acc[r];
    }
    __syncthreads();
    for (int r = wid * 2; r < wid * 2 + 2; r++) {
        float v0 = h1c[r][lane], v1 = h1c[r][lane + 32];
        float s = v0 + v1;
        float ss = v0 * v0 + v1 * v1;
        #pragma unroll
        for (int o = 16; o >= 1; o >>= 1) {
            s  += __shfl_xor_sync(0xffffffffu, s, o);
            ss += __shfl_xor_sync(0xffffffffu, ss, o);
        }
        if (lane == 0) {
            float mu = s / 64.f;
            stat[r][0] = mu;
            stat[r][1] = ss / 64.f - mu * mu;
        }
    }
    __syncthreads();
    if (tid < 64) {
        #pragma unroll
        for (int r = 0; r < 8; r++) {
            float mu = stat[r][0], var = stat[r][1];
            float v = (h1c[r][tid] - mu) * rsqrtf(var + 1e-5f) * cg[tid] + cbe[tid];
            h1c[r][tid] = fmaxf(v, 0.f);
        }
    }
    __syncthreads();
    {
        int j = tid & 31, rr = tid >> 5;
        for (int rp = 0; rp < 2; rp++) {
            int r = rp * 4 + rr;
            float a = cb2[j];
            for (int i = 0; i < 64; i++) a = fmaf(h1c[r][i], cW2[i * 32 + j], a);
            h2c[r][j] = fmaxf(a, 0.f);
        }
    }
    __syncthreads();
    for (int r = wid * 2; r < wid * 2 + 2; r++) {
        float a = h2c[r][lane] * cW3[lane];
        #pragma unroll
        for (int o = 16; o >= 1; o >>= 1) a += __shfl_xor_sync(0xffffffffu, a, o);
        if (lane == 0) csc[r] = 1.f / (1.f + expf(-(a + cb3[0])));
    }
    __syncthreads();

    if (tid < 8) {
        int srow = (row0 + tid) & (SEQ - 1);
        float pos = 0.8f + 0.4f * (float)srow / 1023.f;
        float score = (0.7f * gsc[tid] + 0.3f * csc[tid]) * pos;
        int T = (int)ceilf(score * 20.f);
        T = min(max(T, 1), TMAXS);
        g_T[row0 + tid] = T;
    }
}

// ---------------------------------------------------------------------------
// Improved fp32 GEMM core: BM=128, BN=64, BK=16, double-buffered smem,
// register-staged global loads, 1 barrier per BK.
// Thread map: 256 threads, tx=t&15 (n: tx*4), ty=t>>4 (m: ty*4 and 64+ty*4).
// acc[8][4]. A staged transposed As[k][m] (pad 132), B as Bs[k][n].
// ---------------------------------------------------------------------------
#define GM_PAD 132

__device__ __forceinline__ void gemm_core_12864(
    const float* __restrict__ Aptr,   // A row base: &A[bm][0], row stride EMB
    const float* __restrict__ Bptr,   // W base: &W[0][bn]
    float As[2][16 * GM_PAD], float Bs[2][16 * 64],
    float acc[8][4], int t)
{
    const int tx = t & 15, ty = t >> 4;
    const int am = t >> 1, ak = (t & 1) * 8;      // A: row am, k-offset ak..ak+7
    const int bk = t >> 4, bn4 = (t & 15) * 4;    // B: row bk, cols bn4..bn4+3

    const float* Ag = Aptr + (size_t)am * EMB + ak;
    const float* Bg = Bptr + (size_t)bk * EMB + bn4;

    float4 a0 = *(const float4*)(Ag);
    float4 a1 = *(const float4*)(Ag + 4);
    float4 b0 = *(const float4*)(Bg);

    // store buf 0
    As[0][(ak + 0) * GM_PAD + am] = a0.x;
    As[0][(ak + 1) * GM_PAD + am] = a0.y;
    As[0][(ak + 2) * GM_PAD + am] = a0.z;
    As[0][(ak + 3) * GM_PAD + am] = a0.w;
    As[0][(ak + 4) * GM_PAD + am] = a1.x;
    As[0][(ak + 5) * GM_PAD + am] = a1.y;
    As[0][(ak + 6) * GM_PAD + am] = a1.z;
    As[0][(ak + 7) * GM_PAD + am] = a1.w;
    *(float4*)&Bs[0][bk * 64 + bn4] = b0;
    __syncthreads();

    #pragma unroll 1
    for (int kt = 0; kt < EMB / 16; kt++) {
        const int cur = kt & 1, nxt = cur ^ 1;
        if (kt < EMB / 16 - 1) {
            a0 = *(const float4*)(Ag + (kt + 1) * 16);
            a1 = *(const float4*)(Ag + (kt + 1) * 16 + 4);
            b0 = *(const float4*)(Bg + (size_t)(kt + 1) * 16 * EMB);
        }
        #pragma unroll
        for (int k = 0; k < 16; k++) {
            float a[8], b[4];
            *(float4*)(a)     = *(const float4*)&As[cur][k * GM_PAD + ty * 4];
            *(float4*)(a + 4) = *(const float4*)&As[cur][k * GM_PAD + 64 + ty * 4];
            *(float4*)(b)     = *(const float4*)&Bs[cur][k * 64 + tx * 4];
            #pragma unroll
            for (int i = 0; i < 8; i++)
                #pragma unroll
                for (int j = 0; j < 4; j++)
                    acc[i][j] = fmaf(a[i], b[j], acc[i][j]);
        }
        if (kt < EMB / 16 - 1) {
            As[nxt][(ak + 0) * GM_PAD + am] = a0.x;
            As[nxt][(ak + 1) * GM_PAD + am] = a0.y;
            As[nxt][(ak + 2) * GM_PAD + am] = a0.z;
            As[nxt][(ak + 3) * GM_PAD + am] = a0.w;
            As[nxt][(ak + 4) * GM_PAD + am] = a1.x;
            As[nxt][(ak + 5) * GM_PAD + am] = a1.y;
            As[nxt][(ak + 6) * GM_PAD + am] = a1.z;
            As[nxt][(ak + 7) * GM_PAD + am] = a1.w;
            *(float4*)&Bs[nxt][bk * 64 + bn4] = b0;
            __syncthreads();
        }
    }
}

// ---------------------------------------------------------------------------
// Kernel B: fused QKV GEMM + LIF spike-sum epilogue.
// grid (EMB/64, MROWS/128, 3)
// ---------------------------------------------------------------------------
__global__ __launch_bounds__(256, 2) void qkv_kernel(
    const float* __restrict__ x,
    const float* __restrict__ Wq, const float* __restrict__ Wk, const float* __restrict__ Wv,
    const float* __restrict__ aq, const float* __restrict__ bq,
    const float* __restrict__ ak_, const float* __restrict__ bk_,
    const float* __restrict__ av, const float* __restrict__ bv)
{
    __shared__ float As[2][16 * GM_PAD];
    __shared__ float Bs[2][16 * 64];

    const int z = blockIdx.z;
    const float* W = (z == 0) ? Wq : ((z == 1) ? Wk : Wv);
    float* out = (z == 0) ? g_q : ((z == 1) ? g_k : g_v);
    const float alpha = ((z == 0) ? aq : ((z == 1) ? ak_ : av))[0];
    const float beta  = ((z == 0) ? bq : ((z == 1) ? bk_ : bv))[0];
    const float vscale = (z == 2) ? (1.f / 20.f) : 1.f;

    const int t = threadIdx.x;
    const int tx = t & 15, ty = t >> 4;
    const int bm = blockIdx.y * 128, bn = blockIdx.x * 64;

    float acc[8][4];
    #pragma unroll
    for (int i = 0; i < 8; i++)
        #pragma unroll
        for (int j = 0; j < 4; j++) acc[i][j] = 0.f;

    gemm_core_12864(x + (size_t)bm * EMB, W + bn, As, Bs, acc, t);

    // LIF epilogue: exact — dynamics at t >= T_i never contribute to acc.
    #pragma unroll
    for (int i = 0; i < 8; i++) {
        const int r = bm + ((i < 4) ? (ty * 4 + i) : (64 + ty * 4 + (i - 4)));
        const int T = g_T[r];
        float iv[4], vv[4], sacc[4];
        #pragma unroll
        for (int j = 0; j < 4; j++) { iv[j] = 0.f; vv[j] = 0.f; sacc[j] = 0.f; }
        for (int tt = 0; tt < T; tt++) {
            #pragma unroll
            for (int j = 0; j < 4; j++) {
                iv[j] = fmaf(alpha, iv[j], acc[i][j]);
                vv[j] = fmaf(beta, vv[j], iv[j]);
                float sp = (vv[j] >= 1.f) ? 1.f : 0.f;
                sacc[j] += sp;
                vv[j] *= (1.f - sp);
            }
        }
        *(float4*)(out + (size_t)r * EMB + bn + tx * 4) =
            make_float4(sacc[0] * vscale, sacc[1] * vscale, sacc[2] * vscale, sacc[3] * vscale);
    }
}

// ---------------------------------------------------------------------------
// Kernel C: flash attention, fp32 (unchanged from R1).
// ---------------------------------------------------------------------------
#define ATTN_SMEM_FLOATS (64 * 132 + 64 * 68 + 64 * 68 + 128 * 68)

__global__ __launch_bounds__(256) void attn_kernel()
{
    extern __shared__ float sm[];
    float* Qs = sm;                    // [64][132]  Qs[d][r]
    float* Ks = Qs + 64 * 132;         // [64][68]   Ks[d][j]
    float* Vs = Ks + 64 * 68;          // [64][68]   Vs[j][d]
    float* Ps = Vs + 64 * 68;          // [128][68]  Ps[r][j]

    const int b = blockIdx.z, h = blockIdx.y;
    const int q0 = blockIdx.x * 128;
    const int t = threadIdx.x, tx = t & 15, ty = t >> 4;

    const float* Qg = g_q + (size_t)(b * SEQ + q0) * EMB + h * HD;
    const float* Kg = g_k + (size_t)(b * SEQ) * EMB + h * HD;
    const float* Vg = g_v + (size_t)(b * SEQ) * EMB + h * HD;

    #pragma unroll
    for (int it = 0; it < 8; it++) {
        int idx = it * 256 + t;
        int r = idx >> 4, dq = idx & 15;
        float4 q4 = *(const float4*)(Qg + (size_t)r * EMB + dq * 4);
        Qs[(dq * 4 + 0) * 132 + r] = q4.x;
        Qs[(dq * 4 + 1) * 132 + r] = q4.y;
        Qs[(dq * 4 + 2) * 132 + r] = q4.z;
        Qs[(dq * 4 + 3) * 132 + r] = q4.w;
    }

    float m_[8], l_[8], o_[8][4];
    #pragma unroll
    for (int i = 0; i < 8; i++) {
        m_[i] = -1e30f; l_[i] = 0.f;
        #pragma unroll
        for (int j = 0; j < 4; j++) o_[i][j] = 0.f;
    }

    for (int j0 = 0; j0 < SEQ; j0 += 64) {
        __syncthreads();
        #pragma unroll
        for (int it = 0; it < 4; it++) {
            int idx = it * 256 + t;
            int j = idx >> 4, dq = idx & 15;
            float4 k4 = *(const float4*)(Kg + (size_t)(j0 + j) * EMB + dq * 4);
            Ks[(dq * 4 + 0) * 68 + j] = k4.x;
            Ks[(dq * 4 + 1) * 68 + j] = k4.y;
            Ks[(dq * 4 + 2) * 68 + j] = k4.z;
            Ks[(dq * 4 + 3) * 68 + j] = k4.w;
            float4 v4 = *(const float4*)(Vg + (size_t)(j0 + j) * EMB + dq * 4);
            *(float4*)&Vs[j * 68 + dq * 4] = v4;
        }
        __syncthreads();

        float s[8][4];
        #pragma unroll
        for (int i = 0; i < 8; i++)
            #pragma unroll
            for (int j = 0; j < 4; j++) s[i][j] = 0.f;
        #pragma unroll 16
        for (int d = 0; d < 64; d++) {
            float a[8], bb[4];
            *(float4*)(a)     = *(float4*)&Qs[d * 132 + ty * 4];
            *(float4*)(a + 4) = *(float4*)&Qs[d * 132 + 64 + ty * 4];
            *(float4*)(bb)    = *(float4*)&Ks[d * 68 + tx * 4];
            #pragma unroll
            for (int i = 0; i < 8; i++)
                #pragma unroll
                for (int j = 0; j < 4; j++)
                    s[i][j] = fmaf(a[i], bb[j], s[i][j]);
        }

        #pragma unroll
        for (int i = 0; i < 8; i++) {
            float mx = -1e30f;
            #pragma unroll
            for (int j = 0; j < 4; j++) {
                s[i][j] *= 0.125f;
                mx = fmaxf(mx, s[i][j]);
            }
            #pragma unroll
            for (int o = 8; o >= 1; o >>= 1)
                mx = fmaxf(mx, __shfl_xor_sync(0xffffffffu, mx, o));
            float mn = fmaxf(m_[i], mx);
            float fac = __expf(m_[i] - mn);
            float sum = 0.f;
            #pragma unroll
            for (int j = 0; j < 4; j++) {
                float p = __expf(s[i][j] - mn);
                s[i][j] = p;
                sum += p;
            }
            #pragma unroll
            for (int o = 8; o >= 1; o >>= 1)
                sum += __shfl_xor_sync(0xffffffffu, sum, o);
            l_[i] = l_[i] * fac + sum;
            m_[i] = mn;
            #pragma unroll
            for (int j = 0; j < 4; j++) o_[i][j] *= fac;
        }

        #pragma unroll
        for (int i = 0; i < 8; i++) {
            int r = (i < 4) ? (ty * 4 + i) : (64 + ty * 4 + (i - 4));
            *(float4*)&Ps[r * 68 + tx * 4] = make_float4(s[i][0], s[i][1], s[i][2], s[i][3]);
        }
        __syncthreads();

        #pragma unroll 8
        for (int j = 0; j < 64; j++) {
            float bb[4];
            *(float4*)bb = *(float4*)&Vs[j * 68 + tx * 4];
            #pragma unroll
            for (int i = 0; i < 8; i++) {
                int r = (i < 4) ? (ty * 4 + i) : (64 + ty * 4 + (i - 4));
                float a = Ps[r * 68 + j];
                o_[i][0] = fmaf(a, bb[0], o_[i][0]);
                o_[i][1] = fmaf(a, bb[1], o_[i][1]);
                o_[i][2] = fmaf(a, bb[2], o_[i][2]);
                o_[i][3] = fmaf(a, bb[3], o_[i][3]);
            }
        }
    }

    float* Og = g_attn + (size_t)(b * SEQ + q0) * EMB + h * HD;
    #pragma unroll
    for (int i = 0; i < 8; i++) {
        int r = (i < 4) ? (ty * 4 + i) : (64 + ty * 4 + (i - 4));
        float rl = 1.f / l_[i];
        *(float4*)(Og + (size_t)r * EMB + tx * 4) =
            make_float4(o_[i][0] * rl, o_[i][1] * rl, o_[i][2] * rl, o_[i][3] * rl);
    }
}

// ---------------------------------------------------------------------------
// Kernel D: output projection  out = g_attn @ Wo + bo  (new GEMM core)
// grid (EMB/64, MROWS/128)
// ---------------------------------------------------------------------------
__global__ __launch_bounds__(256, 2) void proj_kernel(
    const float* __restrict__ Wo, const float* __restrict__ bo, float* __restrict__ out)
{
    __shared__ float As[2][16 * GM_PAD];
    __shared__ float Bs[2][16 * 64];

    const int t = threadIdx.x;
    const int tx = t & 15, ty = t >> 4;
    const int bm = blockIdx.y * 128, bn = blockIdx.x * 64;

    float acc[8][4];
    #pragma unroll
    for (int i = 0; i < 8; i++)
        #pragma unroll
        for (int j = 0; j < 4; j++) acc[i][j] = 0.f;

    gemm_core_12864(g_attn + (size_t)bm * EMB, Wo + bn, As, Bs, acc, t);

    float4 bo0 = *(const float4*)(bo + bn + tx * 4);
    #pragma unroll
    for (int i = 0; i < 8; i++) {
        int r = bm + ((i < 4) ? (ty * 4 + i) : (64 + ty * 4 + (i - 4)));
        *(float4*)(out + (size_t)r * EMB + bn + tx * 4) =
            make_float4(acc[i][0] + bo0.x, acc[i][1] + bo0.y,
                        acc[i][2] + bo0.z, acc[i][3] + bo0.w);
    }
}

// ---------------------------------------------------------------------------
extern "C" void kernel_launch(void* const* d_in, const int* in_sizes, int n_in,
                              void* d_out, int out_size)
{
    (void)in_sizes; (void)n_in; (void)out_size;
    const float* x   = (const float*)d_in[0];
    const float* Wq  = (const float*)d_in[1];
    const float* Wk  = (const float*)d_in[2];
    const float* Wv  = (const float*)d_in[3];
    const float* Wo  = (const float*)d_in[4];
    const float* bo  = (const float*)d_in[5];
    const float* gW1 = (const float*)d_in[6];
    const float* gb1 = (const float*)d_in[7];
    const float* gg  = (const float*)d_in[8];
    const float* gbe = (const float*)d_in[9];
    const float* gW2 = (const float*)d_in[10];
    const float* gb2 = (const float*)d_in[11];
    const float* gW3 = (const float*)d_in[12];
    const float* gb3 = (const float*)d_in[13];
    const float* cW1 = (const float*)d_in[14];
    const float* cb1 = (const float*)d_in[15];
    const float* cg  = (const float*)d_in[16];
    const float* cbe = (const float*)d_in[17];
    const float* cW2 = (const float*)d_in[18];
    const float* cb2 = (const float*)d_in[19];
    const float* cW3 = (const float*)d_in[20];
    const float* cb3 = (const float*)d_in[21];
    const float* aq  = (const float*)d_in[22];
    const float* bq  = (const float*)d_in[23];
    const float* ak  = (const float*)d_in[24];
    const float* bk  = (const float*)d_in[25];
    const float* av  = (const float*)d_in[26];
    const float* bv  = (const float*)d_in[27];
    float* out = (float*)d_out;

    const int attn_smem = ATTN_SMEM_FLOATS * (int)sizeof(float);  // 103424 B
    cudaFuncSetAttribute((const void*)attn_kernel,
                         cudaFuncAttributeMaxDynamicSharedMemorySize, attn_smem);

    gate_kernel<<<MROWS / 8, 128>>>(x, gW1, gb1, gg, gbe, gW2, gb2, gW3, gb3,
                                    cW1, cb1, cg, cbe, cW2, cb2, cW3, cb3);

    qkv_kernel<<<dim3(EMB / 64, MROWS / 128, 3), 256>>>(x, Wq, Wk, Wv,
                                                        aq, bq, ak, bk, av, bv);

    attn_kernel<<<dim3(SEQ / 128, NH, BCNT), 256, attn_smem>>>();

    proj_kernel<<<dim3(EMB / 64, MROWS / 128), 256>>>(Wo, bo, out);
}

// round 6
// speedup vs baseline: 1.5795x; 1.5413x over previous
#include <cuda_runtime.h>
#include <cuda_bf16.h>
#include <math.h>
#include <stdint.h>

#define BCNT  4
#define SEQ   1024
#define EMB   512
#define NH    8
#define HD    64
#define MROWS 4096
#define TMAXS 20

// scratch (static device globals; allocation-free per harness rules)
__device__ __nv_bfloat16 g_qb[MROWS * EMB];   // spike counts (exact ints in bf16)
__device__ __nv_bfloat16 g_kb[MROWS * EMB];
__device__ __nv_bfloat16 g_vb[MROWS * EMB];   // RAW spike counts (no /20)
__device__ float g_attn[MROWS * EMB];
__device__ int   g_T[MROWS];

// ===========================================================================
// PTX helpers (baseline PTX only: cp.async sm_80, ldmatrix sm_75, mma sm_80)
// ===========================================================================
__device__ __forceinline__ uint32_t smem_u32(const void* p) {
    uint32_t a;
    asm("{ .reg .u64 t; cvta.to.shared.u64 t, %1; cvt.u32.u64 %0, t; }" : "=r"(a) : "l"(p));
    return a;
}

#define CP_ASYNC16(dst, src) \
    asm volatile("cp.async.cg.shared.global [%0], [%1], 16;" :: "r"(dst), "l"(src))
#define CP_COMMIT() asm volatile("cp.async.commit_group;" ::: "memory")
#define CP_WAIT(n)  asm volatile("cp.async.wait_group %0;" :: "n"(n) : "memory")

#define LDMATRIX_X2(r0, r1, addr) \
    asm volatile("ldmatrix.sync.aligned.m8n8.x2.shared.b16 {%0,%1}, [%2];" \
                 : "=r"(r0), "=r"(r1) : "r"(addr))
#define LDMATRIX_X2_T(r0, r1, addr) \
    asm volatile("ldmatrix.sync.aligned.m8n8.x2.trans.shared.b16 {%0,%1}, [%2];" \
                 : "=r"(r0), "=r"(r1) : "r"(addr))

#define MMA_BF16(d, a, b0, b1) \
    asm volatile("mma.sync.aligned.m16n8k16.row.col.f32.bf16.bf16.f32 " \
                 "{%0,%1,%2,%3}, {%4,%5,%6,%7}, {%8,%9}, {%0,%1,%2,%3};" \
                 : "+f"((d)[0]), "+f"((d)[1]), "+f"((d)[2]), "+f"((d)[3]) \
                 : "r"((a)[0]), "r"((a)[1]), "r"((a)[2]), "r"((a)[3]), \
                   "r"(b0), "r"(b1))

__device__ __forceinline__ uint32_t pack_bf2(float lo, float hi) {
    __nv_bfloat162 v = __floats2bfloat162_rn(lo, hi);   // .x = lo half (low 16 bits)
    return *(uint32_t*)&v;
}

// ===========================================================================
// Kernel A: gate + complexity MLPs -> adaptive window T_i (unchanged)
// ===========================================================================
__global__ __launch_bounds__(128) void gate_kernel(
    const float* __restrict__ x,
    const float* __restrict__ gW1, const float* __restrict__ gb1,
    const float* __restrict__ gg,  const float* __restrict__ gbe,
    const float* __restrict__ gW2, const float* __restrict__ gb2,
    const float* __restrict__ gW3, const float* __restrict__ gb3,
    const float* __restrict__ cW1, const float* __restrict__ cb1,
    const float* __restrict__ cg,  const float* __restrict__ cbe,
    const float* __restrict__ cW2, const float* __restrict__ cb2,
    const float* __restrict__ cW3, const float* __restrict__ cb3)
{
    __shared__ float xs[8][EMB];
    __shared__ float h1[8][128];
    __shared__ float h2[8][64];
    __shared__ float h1c[8][64];
    __shared__ float h2c[8][32];
    __shared__ float stat[8][2];
    __shared__ float gsc[8], csc[8];

    const int tid  = threadIdx.x;
    const int wid  = tid >> 5, lane = tid & 31;
    const int row0 = blockIdx.x * 8;

    for (int i = tid; i < 8 * EMB; i += 128)
        xs[i >> 9][i & 511] = x[row0 * EMB + i];
    __syncthreads();

    {
        float acc[8];
        float bvv = gb1[tid];
        #pragma unroll
        for (int r = 0; r < 8; r++) acc[r] = bvv;
        for (int e = 0; e < EMB; e++) {
            float w = gW1[e * 128 + tid];
            #pragma unroll
            for (int r = 0; r < 8; r++) acc[r] = fmaf(xs[r][e], w, acc[r]);
        }
        #pragma unroll
        for (int r = 0; r < 8; r++) h1[r][tid] = acc[r];
    }
    __syncthreads();
    for (int r = wid * 2; r < wid * 2 + 2; r++) {
        float v0 = h1[r][lane], v1 = h1[r][lane + 32], v2 = h1[r][lane + 64], v3 = h1[r][lane + 96];
        float s = v0 + v1 + v2 + v3;
        float ss = v0 * v0 + v1 * v1 + v2 * v2 + v3 * v3;
        #pragma unroll
        for (int o = 16; o >= 1; o >>= 1) {
            s  += __shfl_xor_sync(0xffffffffu, s, o);
            ss += __shfl_xor_sync(0xffffffffu, ss, o);
        }
        if (lane == 0) {
            float mu = s / 128.f;
            stat[r][0] = mu;
            stat[r][1] = ss / 128.f - mu * mu;
        }
    }
    __syncthreads();
    #pragma unroll
    for (int r = 0; r < 8; r++) {
        float mu = stat[r][0], var = stat[r][1];
        float v = (h1[r][tid] - mu) * rsqrtf(var + 1e-5f) * gg[tid] + gbe[tid];
        h1[r][tid] = fmaxf(v, 0.f);
    }
    __syncthreads();
    {
        int j = tid & 63, rr = tid >> 6;
        for (int rp = 0; rp < 4; rp++) {
            int r = rp * 2 + rr;
            float a = gb2[j];
            for (int i = 0; i < 128; i++) a = fmaf(h1[r][i], gW2[i * 64 + j], a);
            h2[r][j] = fmaxf(a, 0.f);
        }
    }
    __syncthreads();
    for (int r = wid * 2; r < wid * 2 + 2; r++) {
        float a = h2[r][lane] * gW3[lane] + h2[r][lane + 32] * gW3[lane + 32];
        #pragma unroll
        for (int o = 16; o >= 1; o >>= 1) a += __shfl_xor_sync(0xffffffffu, a, o);
        if (lane == 0) gsc[r] = 1.f / (1.f + expf(-(a + gb3[0])));
    }
    __syncthreads();

    if (tid < 64) {
        float acc[8];
        float bvv = cb1[tid];
        #pragma unroll
        for (int r = 0; r < 8; r++) acc[r] = bvv;
        for (int e = 0; e < EMB; e++) {
            float w = cW1[e * 64 + tid];
            #pragma unroll
            for (int r = 0; r < 8; r++) acc[r] = fmaf(xs[r][e], w, acc[r]);
        }
        #pragma unroll
        for (int r = 0; r < 8; r++) h1c[r][tid] = acc[r];
    }
    __syncthreads();
    for (int r = wid * 2; r < wid * 2 + 2; r++) {
        float v0 = h1c[r][lane], v1 = h1c[r][lane + 32];
        float s = v0 + v1;
        float ss = v0 * v0 + v1 * v1;
        #pragma unroll
        for (int o = 16; o >= 1; o >>= 1) {
            s  += __shfl_xor_sync(0xffffffffu, s, o);
            ss += __shfl_xor_sync(0xffffffffu, ss, o);
        }
        if (lane == 0) {
            float mu = s / 64.f;
            stat[r][0] = mu;
            stat[r][1] = ss / 64.f - mu * mu;
        }
    }
    __syncthreads();
    if (tid < 64) {
        #pragma unroll
        for (int r = 0; r < 8; r++) {
            float mu = stat[r][0], var = stat[r][1];
            float v = (h1c[r][tid] - mu) * rsqrtf(var + 1e-5f) * cg[tid] + cbe[tid];
            h1c[r][tid] = fmaxf(v, 0.f);
        }
    }
    __syncthreads();
    {
        int j = tid & 31, rr = tid >> 5;
        for (int rp = 0; rp < 2; rp++) {
            int r = rp * 4 + rr;
            float a = cb2[j];
            for (int i = 0; i < 64; i++) a = fmaf(h1c[r][i], cW2[i * 32 + j], a);
            h2c[r][j] = fmaxf(a, 0.f);
        }
    }
    __syncthreads();
    for (int r = wid * 2; r < wid * 2 + 2; r++) {
        float a = h2c[r][lane] * cW3[lane];
        #pragma unroll
        for (int o = 16; o >= 1; o >>= 1) a += __shfl_xor_sync(0xffffffffu, a, o);
        if (lane == 0) csc[r] = 1.f / (1.f + expf(-(a + cb3[0])));
    }
    __syncthreads();

    if (tid < 8) {
        int srow = (row0 + tid) & (SEQ - 1);
        float pos = 0.8f + 0.4f * (float)srow / 1023.f;
        float score = (0.7f * gsc[tid] + 0.3f * csc[tid]) * pos;
        int T = (int)ceilf(score * 20.f);
        T = min(max(T, 1), TMAXS);
        g_T[row0 + tid] = T;
    }
}

// ===========================================================================
// fp32 GEMM core: BM=128, BN=64, BK=16, double-buffered (unchanged)
// ===========================================================================
#define GM_PAD 132

__device__ __forceinline__ void gemm_core_12864(
    const float* __restrict__ Aptr,
    const float* __restrict__ Bptr,
    float As[2][16 * GM_PAD], float Bs[2][16 * 64],
    float acc[8][4], int t)
{
    const int tx = t & 15, ty = t >> 4;
    const int am = t >> 1, ak = (t & 1) * 8;
    const int bk = t >> 4, bn4 = (t & 15) * 4;

    const float* Ag = Aptr + (size_t)am * EMB + ak;
    const float* Bg = Bptr + (size_t)bk * EMB + bn4;

    float4 a0 = *(const float4*)(Ag);
    float4 a1 = *(const float4*)(Ag + 4);
    float4 b0 = *(const float4*)(Bg);

    As[0][(ak + 0) * GM_PAD + am] = a0.x;
    As[0][(ak + 1) * GM_PAD + am] = a0.y;
    As[0][(ak + 2) * GM_PAD + am] = a0.z;
    As[0][(ak + 3) * GM_PAD + am] = a0.w;
    As[0][(ak + 4) * GM_PAD + am] = a1.x;
    As[0][(ak + 5) * GM_PAD + am] = a1.y;
    As[0][(ak + 6) * GM_PAD + am] = a1.z;
    As[0][(ak + 7) * GM_PAD + am] = a1.w;
    *(float4*)&Bs[0][bk * 64 + bn4] = b0;
    __syncthreads();

    #pragma unroll 1
    for (int kt = 0; kt < EMB / 16; kt++) {
        const int cur = kt & 1, nxt = cur ^ 1;
        if (kt < EMB / 16 - 1) {
            a0 = *(const float4*)(Ag + (kt + 1) * 16);
            a1 = *(const float4*)(Ag + (kt + 1) * 16 + 4);
            b0 = *(const float4*)(Bg + (size_t)(kt + 1) * 16 * EMB);
        }
        #pragma unroll
        for (int k = 0; k < 16; k++) {
            float a[8], b[4];
            *(float4*)(a)     = *(const float4*)&As[cur][k * GM_PAD + ty * 4];
            *(float4*)(a + 4) = *(const float4*)&As[cur][k * GM_PAD + 64 + ty * 4];
            *(float4*)(b)     = *(const float4*)&Bs[cur][k * 64 + tx * 4];
            #pragma unroll
            for (int i = 0; i < 8; i++)
                #pragma unroll
                for (int j = 0; j < 4; j++)
                    acc[i][j] = fmaf(a[i], b[j], acc[i][j]);
        }
        if (kt < EMB / 16 - 1) {
            As[nxt][(ak + 0) * GM_PAD + am] = a0.x;
            As[nxt][(ak + 1) * GM_PAD + am] = a0.y;
            As[nxt][(ak + 2) * GM_PAD + am] = a0.z;
            As[nxt][(ak + 3) * GM_PAD + am] = a0.w;
            As[nxt][(ak + 4) * GM_PAD + am] = a1.x;
            As[nxt][(ak + 5) * GM_PAD + am] = a1.y;
            As[nxt][(ak + 6) * GM_PAD + am] = a1.z;
            As[nxt][(ak + 7) * GM_PAD + am] = a1.w;
            *(float4*)&Bs[nxt][bk * 64 + bn4] = b0;
            __syncthreads();
        }
    }
}

// ===========================================================================
// Kernel B: fused QKV GEMM + LIF spike-sum -> bf16 spike counts (exact ints).
// V stores RAW spike counts (no /20; folded into attention epilogue).
// ===========================================================================
__global__ __launch_bounds__(256, 2) void qkv_kernel(
    const float* __restrict__ x,
    const float* __restrict__ Wq, const float* __restrict__ Wk, const float* __restrict__ Wv,
    const float* __restrict__ aq, const float* __restrict__ bq,
    const float* __restrict__ ak_, const float* __restrict__ bk_,
    const float* __restrict__ av, const float* __restrict__ bv)
{
    __shared__ float As[2][16 * GM_PAD];
    __shared__ float Bs[2][16 * 64];

    const int z = blockIdx.z;
    const float* W = (z == 0) ? Wq : ((z == 1) ? Wk : Wv);
    __nv_bfloat16* out = (z == 0) ? g_qb : ((z == 1) ? g_kb : g_vb);
    const float alpha = ((z == 0) ? aq : ((z == 1) ? ak_ : av))[0];
    const float beta  = ((z == 0) ? bq : ((z == 1) ? bk_ : bv))[0];

    const int t = threadIdx.x;
    const int tx = t & 15, ty = t >> 4;
    const int bm = blockIdx.y * 128, bn = blockIdx.x * 64;

    float acc[8][4];
    #pragma unroll
    for (int i = 0; i < 8; i++)
        #pragma unroll
        for (int j = 0; j < 4; j++) acc[i][j] = 0.f;

    gemm_core_12864(x + (size_t)bm * EMB, W + bn, As, Bs, acc, t);

    #pragma unroll
    for (int i = 0; i < 8; i++) {
        const int r = bm + ((i < 4) ? (ty * 4 + i) : (64 + ty * 4 + (i - 4)));
        const int T = g_T[r];
        float iv[4], vv[4], sacc[4];
        #pragma unroll
        for (int j = 0; j < 4; j++) { iv[j] = 0.f; vv[j] = 0.f; sacc[j] = 0.f; }
        for (int tt = 0; tt < T; tt++) {
            #pragma unroll
            for (int j = 0; j < 4; j++) {
                iv[j] = fmaf(alpha, iv[j], acc[i][j]);
                vv[j] = fmaf(beta, vv[j], iv[j]);
                float sp = (vv[j] >= 1.f) ? 1.f : 0.f;
                sacc[j] += sp;
                vv[j] *= (1.f - sp);
            }
        }
        __nv_bfloat162* o2 = (__nv_bfloat162*)(out + (size_t)r * EMB + bn + tx * 4);
        o2[0] = __nv_bfloat162(__float2bfloat16(sacc[0]), __float2bfloat16(sacc[1]));
        o2[1] = __nv_bfloat162(__float2bfloat16(sacc[2]), __float2bfloat16(sacc[3]));
    }
}

// ===========================================================================
// Kernel C: flash attention with warp-level bf16 MMA (mma.sync m16n8k16).
// CTA = 128 q rows x (b,h); 8 warps; each warp owns 16 q rows.
// KV chunks of 64 keys, cp.async double-buffered. Rows padded to 72 bf16.
//   S = Q@K^T exact (integer bf16 inputs); O += (P_hi + P_lo)@V split-bf16.
// ===========================================================================
#define KVPAD 72

__global__ __launch_bounds__(256) void attn_kernel()
{
    __shared__ __nv_bfloat16 sK[2][64 * KVPAD];
    __shared__ __nv_bfloat16 sV[2][64 * KVPAD];

    const int t = threadIdx.x;
    const int w = t >> 5, lane = t & 31;
    const int g = lane >> 2, tg = lane & 3;
    const int b = blockIdx.z, h = blockIdx.y;
    const int q0 = blockIdx.x * 128;
    const int qrow = q0 + w * 16;

    // ---- Q fragments (A-operand, m16k16 x 4 k-tiles), loaded once ----
    uint32_t qa[4][4];
    {
        const __nv_bfloat16* Qg = g_qb + (size_t)(b * SEQ + qrow) * EMB + h * HD;
        #pragma unroll
        for (int kt = 0; kt < 4; kt++) {
            qa[kt][0] = *(const uint32_t*)(Qg + (size_t)g * EMB + kt * 16 + 2 * tg);
            qa[kt][1] = *(const uint32_t*)(Qg + (size_t)(g + 8) * EMB + kt * 16 + 2 * tg);
            qa[kt][2] = *(const uint32_t*)(Qg + (size_t)g * EMB + kt * 16 + 8 + 2 * tg);
            qa[kt][3] = *(const uint32_t*)(Qg + (size_t)(g + 8) * EMB + kt * 16 + 8 + 2 * tg);
        }
    }

    // ldmatrix lane base addresses
    // K (non-trans): row = nt*8 + (lane&7), col half = ((lane>>3)&1)*8, col base kt*16
    const uint32_t kRowOff = (uint32_t)(lane & 7) * KVPAD + ((lane >> 3) & 1) * 8;
    // V (trans): row = kt2*16 + (lane&15), col base nt*8
    const uint32_t vRowOff = (uint32_t)(lane & 15) * KVPAD;

    const __nv_bfloat16* Kg = g_kb + (size_t)(b * SEQ) * EMB + h * HD;
    const __nv_bfloat16* Vg = g_vb + (size_t)(b * SEQ) * EMB + h * HD;
    const int ldrow = t >> 2, ldsg = t & 3;

    // ---- prefetch chunk 0 ----
    {
        const __nv_bfloat16* kg = Kg + (size_t)ldrow * EMB;
        const __nv_bfloat16* vg = Vg + (size_t)ldrow * EMB;
        uint32_t ks = smem_u32(&sK[0][ldrow * KVPAD]);
        uint32_t vs = smem_u32(&sV[0][ldrow * KVPAD]);
        CP_ASYNC16(ks + ldsg * 16, kg + ldsg * 8);
        CP_ASYNC16(ks + (ldsg + 4) * 16, kg + (ldsg + 4) * 8);
        CP_ASYNC16(vs + ldsg * 16, vg + ldsg * 8);
        CP_ASYNC16(vs + (ldsg + 4) * 16, vg + (ldsg + 4) * 8);
        CP_COMMIT();
    }

    float o[8][4];
    #pragma unroll
    for (int nt = 0; nt < 8; nt++)
        #pragma unroll
        for (int i = 0; i < 4; i++) o[nt][i] = 0.f;
    float mA = -1e30f, mB = -1e30f, lA = 0.f, lB = 0.f;

    #pragma unroll 1
    for (int j = 0; j < 16; j++) {
        const int buf = j & 1;

        // prefetch chunk j+1 into buf^1
        if (j < 15) {
            const int j1 = (j + 1) * 64;
            const __nv_bfloat16* kg = Kg + (size_t)(j1 + ldrow) * EMB;
            const __nv_bfloat16* vg = Vg + (size_t)(j1 + ldrow) * EMB;
            uint32_t ks = smem_u32(&sK[buf ^ 1][ldrow * KVPAD]);
            uint32_t vs = smem_u32(&sV[buf ^ 1][ldrow * KVPAD]);
            CP_ASYNC16(ks + ldsg * 16, kg + ldsg * 8);
            CP_ASYNC16(ks + (ldsg + 4) * 16, kg + (ldsg + 4) * 8);
            CP_ASYNC16(vs + ldsg * 16, vg + ldsg * 8);
            CP_ASYNC16(vs + (ldsg + 4) * 16, vg + (ldsg + 4) * 8);
            CP_COMMIT();
            CP_WAIT(1);   // chunk j resident
        } else {
            CP_WAIT(0);
        }
        __syncthreads();

        // ---- S = Q @ K^T  (exact) ----
        float s[8][4];
        const uint32_t kb = smem_u32(&sK[buf][0]);
        #pragma unroll
        for (int nt = 0; nt < 8; nt++) {
            #pragma unroll
            for (int i = 0; i < 4; i++) s[nt][i] = 0.f;
            #pragma unroll
            for (int kt = 0; kt < 4; kt++) {
                uint32_t k0, k1;
                LDMATRIX_X2(k0, k1, kb + (uint32_t)(nt * 8 * KVPAD + kt * 16) * 2 + kRowOff * 2);
                MMA_BF16(s[nt], qa[kt], k0, k1);
            }
        }

        // ---- online softmax (rows g and g+8; quad = lanes sharing g) ----
        float mxA = -1e30f, mxB = -1e30f;
        #pragma unroll
        for (int nt = 0; nt < 8; nt++) {
            s[nt][0] *= 0.125f; s[nt][1] *= 0.125f;
            s[nt][2] *= 0.125f; s[nt][3] *= 0.125f;
            mxA = fmaxf(mxA, fmaxf(s[nt][0], s[nt][1]));
            mxB = fmaxf(mxB, fmaxf(s[nt][2], s[nt][3]));
        }
        mxA = fmaxf(mxA, __shfl_xor_sync(0xffffffffu, mxA, 1));
        mxA = fmaxf(mxA, __shfl_xor_sync(0xffffffffu, mxA, 2));
        mxB = fmaxf(mxB, __shfl_xor_sync(0xffffffffu, mxB, 1));
        mxB = fmaxf(mxB, __shfl_xor_sync(0xffffffffu, mxB, 2));

        const float mnA = fmaxf(mA, mxA), mnB = fmaxf(mB, mxB);
        const float facA = __expf(mA - mnA), facB = __expf(mB - mnB);
        mA = mnA; mB = mnB;

        float sumA = 0.f, sumB = 0.f;
        #pragma unroll
        for (int nt = 0; nt < 8; nt++) {
            s[nt][0] = __expf(s[nt][0] - mnA);
            s[nt][1] = __expf(s[nt][1] - mnA);
            s[nt][2] = __expf(s[nt][2] - mnB);
            s[nt][3] = __expf(s[nt][3] - mnB);
            sumA += s[nt][0] + s[nt][1];
            sumB += s[nt][2] + s[nt][3];
        }
        sumA += __shfl_xor_sync(0xffffffffu, sumA, 1);
        sumA += __shfl_xor_sync(0xffffffffu, sumA, 2);
        sumB += __shfl_xor_sync(0xffffffffu, sumB, 1);
        sumB += __shfl_xor_sync(0xffffffffu, sumB, 2);
        lA = lA * facA + sumA;
        lB = lB * facB + sumB;

        // rescale O
        #pragma unroll
        for (int nt = 0; nt < 8; nt++) {
            o[nt][0] *= facA; o[nt][1] *= facA;
            o[nt][2] *= facB; o[nt][3] *= facB;
        }

        // ---- split P into bf16 hi/lo A-fragments (k-tile kt2 = n-tiles 2kt2,2kt2+1) ----
        uint32_t phi[4][4], plo[4][4];
        #pragma unroll
        for (int kt2 = 0; kt2 < 4; kt2++) {
            const int n0 = 2 * kt2, n1 = 2 * kt2 + 1;
            float p00 = s[n0][0], p01 = s[n0][1], p02 = s[n0][2], p03 = s[n0][3];
            float p10 = s[n1][0], p11 = s[n1][1], p12 = s[n1][2], p13 = s[n1][3];
            uint32_t h00 = pack_bf2(p00, p01), h01 = pack_bf2(p02, p03);
            uint32_t h10 = pack_bf2(p10, p11), h11 = pack_bf2(p12, p13);
            phi[kt2][0] = h00; phi[kt2][1] = h01; phi[kt2][2] = h10; phi[kt2][3] = h11;
            __nv_bfloat162 b00 = *(__nv_bfloat162*)&h00, b01 = *(__nv_bfloat162*)&h01;
            __nv_bfloat162 b10 = *(__nv_bfloat162*)&h10, b11 = *(__nv_bfloat162*)&h11;
            plo[kt2][0] = pack_bf2(p00 - __bfloat162float(b00.x), p01 - __bfloat162float(b00.y));
            plo[kt2][1] = pack_bf2(p02 - __bfloat162float(b01.x), p03 - __bfloat162float(b01.y));
            plo[kt2][2] = pack_bf2(p10 - __bfloat162float(b10.x), p11 - __bfloat162float(b10.y));
            plo[kt2][3] = pack_bf2(p12 - __bfloat162float(b11.x), p13 - __bfloat162float(b11.y));
        }

        // ---- O += (P_hi + P_lo) @ V ----
        const uint32_t vb = smem_u32(&sV[buf][0]);
        #pragma unroll
        for (int kt2 = 0; kt2 < 4; kt2++) {
            #pragma unroll
            for (int nt = 0; nt < 8; nt++) {
                uint32_t v0, v1;
                LDMATRIX_X2_T(v0, v1, vb + (uint32_t)(kt2 * 16 * KVPAD + nt * 8) * 2 + vRowOff * 2);
                MMA_BF16(o[nt], phi[kt2], v0, v1);
                MMA_BF16(o[nt], plo[kt2], v0, v1);
            }
        }
        __syncthreads();   // all warps done with buf before it is refilled
    }

    // ---- epilogue: normalize, fold v_mean = spikes/20 ----
    {
        const float invA = 1.f / (lA * 20.f), invB = 1.f / (lB * 20.f);
        float* OgA = g_attn + (size_t)(b * SEQ + qrow + g) * EMB + h * HD;
        float* OgB = g_attn + (size_t)(b * SEQ + qrow + g + 8) * EMB + h * HD;
        #pragma unroll
        for (int nt = 0; nt < 8; nt++) {
            *(float2*)(OgA + nt * 8 + 2 * tg) = make_float2(o[nt][0] * invA, o[nt][1] * invA);
            *(float2*)(OgB + nt * 8 + 2 * tg) = make_float2(o[nt][2] * invB, o[nt][3] * invB);
        }
    }
}

// ===========================================================================
// Kernel D: output projection  out = g_attn @ Wo + bo
// ===========================================================================
__global__ __launch_bounds__(256, 2) void proj_kernel(
    const float* __restrict__ Wo, const float* __restrict__ bo, float* __restrict__ out)
{
    __shared__ float As[2][16 * GM_PAD];
    __shared__ float Bs[2][16 * 64];

    const int t = threadIdx.x;
    const int tx = t & 15, ty = t >> 4;
    const int bm = blockIdx.y * 128, bn = blockIdx.x * 64;

    float acc[8][4];
    #pragma unroll
    for (int i = 0; i < 8; i++)
        #pragma unroll
        for (int j = 0; j < 4; j++) acc[i][j] = 0.f;

    gemm_core_12864(g_attn + (size_t)bm * EMB, Wo + bn, As, Bs, acc, t);

    float4 bo0 = *(const float4*)(bo + bn + tx * 4);
    #pragma unroll
    for (int i = 0; i < 8; i++) {
        int r = bm + ((i < 4) ? (ty * 4 + i) : (64 + ty * 4 + (i - 4)));
        *(float4*)(out + (size_t)r * EMB + bn + tx * 4) =
            make_float4(acc[i][0] + bo0.x, acc[i][1] + bo0.y,
                        acc[i][2] + bo0.z, acc[i][3] + bo0.w);
    }
}

// ===========================================================================
extern "C" void kernel_launch(void* const* d_in, const int* in_sizes, int n_in,
                              void* d_out, int out_size)
{
    (void)in_sizes; (void)n_in; (void)out_size;
    const float* x   = (const float*)d_in[0];
    const float* Wq  = (const float*)d_in[1];
    const float* Wk  = (const float*)d_in[2];
    const float* Wv  = (const float*)d_in[3];
    const float* Wo  = (const float*)d_in[4];
    const float* bo  = (const float*)d_in[5];
    const float* gW1 = (const float*)d_in[6];
    const float* gb1 = (const float*)d_in[7];
    const float* gg  = (const float*)d_in[8];
    const float* gbe = (const float*)d_in[9];
    const float* gW2 = (const float*)d_in[10];
    const float* gb2 = (const float*)d_in[11];
    const float* gW3 = (const float*)d_in[12];
    const float* gb3 = (const float*)d_in[13];
    const float* cW1 = (const float*)d_in[14];
    const float* cb1 = (const float*)d_in[15];
    const float* cg  = (const float*)d_in[16];
    const float* cbe = (const float*)d_in[17];
    const float* cW2 = (const float*)d_in[18];
    const float* cb2 = (const float*)d_in[19];
    const float* cW3 = (const float*)d_in[20];
    const float* cb3 = (const float*)d_in[21];
    const float* aq  = (const float*)d_in[22];
    const float* bq  = (const float*)d_in[23];
    const float* ak  = (const float*)d_in[24];
    const float* bk  = (const float*)d_in[25];
    const float* av  = (const float*)d_in[26];
    const float* bv  = (const float*)d_in[27];
    float* out = (float*)d_out;

    gate_kernel<<<MROWS / 8, 128>>>(x, gW1, gb1, gg, gbe, gW2, gb2, gW3, gb3,
                                    cW1, cb1, cg, cbe, cW2, cb2, cW3, cb3);

    qkv_kernel<<<dim3(EMB / 64, MROWS / 128, 3), 256>>>(x, Wq, Wk, Wv,
                                                        aq, bq, ak, bk, av, bv);

    attn_kernel<<<dim3(SEQ / 128, NH, BCNT), 256>>>();

    proj_kernel<<<dim3(EMB / 64, MROWS / 128), 256>>>(Wo, bo, out);
}

// round 9
// speedup vs baseline: 1.6603x; 1.0511x over previous
#include <cuda_runtime.h>
#include <cuda_bf16.h>
#include <math.h>
#include <stdint.h>

#define BCNT  4
#define SEQ   1024
#define EMB   512
#define NH    8
#define HD    64
#define MROWS 4096
#define TMAXS 20

// scratch (static device globals; allocation-free per harness rules)
__device__ __nv_bfloat16 g_qb[MROWS * EMB];   // spike counts (exact ints in bf16)
__device__ __nv_bfloat16 g_kb[MROWS * EMB];
__device__ __nv_bfloat16 g_vb[MROWS * EMB];   // RAW spike counts (no /20)
__device__ float g_attn[MROWS * EMB];
__device__ int   g_T[MROWS];

// ===========================================================================
// PTX helpers
// ===========================================================================
__device__ __forceinline__ uint32_t smem_u32(const void* p) {
    uint32_t a;
    asm("{ .reg .u64 t; cvta.to.shared.u64 t, %1; cvt.u32.u64 %0, t; }" : "=r"(a) : "l"(p));
    return a;
}

#define CP_ASYNC16(dst, src) \
    asm volatile("cp.async.cg.shared.global [%0], [%1], 16;" :: "r"(dst), "l"(src))
#define CP_COMMIT() asm volatile("cp.async.commit_group;" ::: "memory")
#define CP_WAIT(n)  asm volatile("cp.async.wait_group %0;" :: "n"(n) : "memory")

#define LDMATRIX_X2(r0, r1, addr) \
    asm volatile("ldmatrix.sync.aligned.m8n8.x2.shared.b16 {%0,%1}, [%2];" \
                 : "=r"(r0), "=r"(r1) : "r"(addr))
#define LDMATRIX_X2_T(r0, r1, addr) \
    asm volatile("ldmatrix.sync.aligned.m8n8.x2.trans.shared.b16 {%0,%1}, [%2];" \
                 : "=r"(r0), "=r"(r1) : "r"(addr))

#define MMA_BF16(d, a, b0, b1) \
    asm volatile("mma.sync.aligned.m16n8k16.row.col.f32.bf16.bf16.f32 " \
                 "{%0,%1,%2,%3}, {%4,%5,%6,%7}, {%8,%9}, {%0,%1,%2,%3};" \
                 : "+f"((d)[0]), "+f"((d)[1]), "+f"((d)[2]), "+f"((d)[3]) \
                 : "r"((a)[0]), "r"((a)[1]), "r"((a)[2]), "r"((a)[3]), \
                   "r"(b0), "r"(b1))

#define MMA_TF32(d, a, b0, b1) \
    asm volatile("mma.sync.aligned.m16n8k8.row.col.f32.tf32.tf32.f32 " \
                 "{%0,%1,%2,%3}, {%4,%5,%6,%7}, {%8,%9}, {%0,%1,%2,%3};" \
                 : "+f"((d)[0]), "+f"((d)[1]), "+f"((d)[2]), "+f"((d)[3]) \
                 : "r"((a)[0]), "r"((a)[1]), "r"((a)[2]), "r"((a)[3]), \
                   "r"(b0), "r"(b1))

__device__ __forceinline__ uint32_t pack_bf2(float lo, float hi) {
    __nv_bfloat162 v = __floats2bfloat162_rn(lo, hi);
    return *(uint32_t*)&v;
}

__device__ __forceinline__ void split_tf32(float x, uint32_t& hi, uint32_t& lo) {
    asm("cvt.rna.tf32.f32 %0, %1;" : "=r"(hi) : "f"(x));
    float r = x - __uint_as_float(hi);
    asm("cvt.rna.tf32.f32 %0, %1;" : "=r"(lo) : "f"(r));
}

// packed fp32x2 FMA (Blackwell base-family PTX). Each lane = IEEE fp32 fma.rn.
__device__ __forceinline__ void fma2(uint64_t& c, uint64_t a, uint64_t b) {
    asm("fma.rn.f32x2 %0, %1, %2, %0;" : "+l"(c) : "l"(a), "l"(b));
}
__device__ __forceinline__ uint64_t dup2(float x) {
    uint64_t r;
    asm("mov.b64 %0, {%1, %1};" : "=l"(r) : "f"(x));
    return r;
}
__device__ __forceinline__ void unpack2(uint64_t v, float& lo, float& hi) {
    asm("mov.b64 {%0, %1}, %2;" : "=f"(lo), "=f"(hi) : "l"(v));
}

// ===========================================================================
// Kernel A: gate + complexity MLPs -> adaptive window T_i (unchanged)
// ===========================================================================
__global__ __launch_bounds__(128) void gate_kernel(
    const float* __restrict__ x,
    const float* __restrict__ gW1, const float* __restrict__ gb1,
    const float* __restrict__ gg,  const float* __restrict__ gbe,
    const float* __restrict__ gW2, const float* __restrict__ gb2,
    const float* __restrict__ gW3, const float* __restrict__ gb3,
    const float* __restrict__ cW1, const float* __restrict__ cb1,
    const float* __restrict__ cg,  const float* __restrict__ cbe,
    const float* __restrict__ cW2, const float* __restrict__ cb2,
    const float* __restrict__ cW3, const float* __restrict__ cb3)
{
    __shared__ float xs[8][EMB];
    __shared__ float h1[8][128];
    __shared__ float h2[8][64];
    __shared__ float h1c[8][64];
    __shared__ float h2c[8][32];
    __shared__ float stat[8][2];
    __shared__ float gsc[8], csc[8];

    const int tid  = threadIdx.x;
    const int wid  = tid >> 5, lane = tid & 31;
    const int row0 = blockIdx.x * 8;

    for (int i = tid; i < 8 * EMB; i += 128)
        xs[i >> 9][i & 511] = x[row0 * EMB + i];
    __syncthreads();

    {
        float acc[8];
        float bvv = gb1[tid];
        #pragma unroll
        for (int r = 0; r < 8; r++) acc[r] = bvv;
        for (int e = 0; e < EMB; e++) {
            float w = gW1[e * 128 + tid];
            #pragma unroll
            for (int r = 0; r < 8; r++) acc[r] = fmaf(xs[r][e], w, acc[r]);
        }
        #pragma unroll
        for (int r = 0; r < 8; r++) h1[r][tid] = acc[r];
    }
    __syncthreads();
    for (int r = wid * 2; r < wid * 2 + 2; r++) {
        float v0 = h1[r][lane], v1 = h1[r][lane + 32], v2 = h1[r][lane + 64], v3 = h1[r][lane + 96];
        float s = v0 + v1 + v2 + v3;
        float ss = v0 * v0 + v1 * v1 + v2 * v2 + v3 * v3;
        #pragma unroll
        for (int o = 16; o >= 1; o >>= 1) {
            s  += __shfl_xor_sync(0xffffffffu, s, o);
            ss += __shfl_xor_sync(0xffffffffu, ss, o);
        }
        if (lane == 0) {
            float mu = s / 128.f;
            stat[r][0] = mu;
            stat[r][1] = ss / 128.f - mu * mu;
        }
    }
    __syncthreads();
    #pragma unroll
    for (int r = 0; r < 8; r++) {
        float mu = stat[r][0], var = stat[r][1];
        float v = (h1[r][tid] - mu) * rsqrtf(var + 1e-5f) * gg[tid] + gbe[tid];
        h1[r][tid] = fmaxf(v, 0.f);
    }
    __syncthreads();
    {
        int j = tid & 63, rr = tid >> 6;
        for (int rp = 0; rp < 4; rp++) {
            int r = rp * 2 + rr;
            float a = gb2[j];
            for (int i = 0; i < 128; i++) a = fmaf(h1[r][i], gW2[i * 64 + j], a);
            h2[r][j] = fmaxf(a, 0.f);
        }
    }
    __syncthreads();
    for (int r = wid * 2; r < wid * 2 + 2; r++) {
        float a = h2[r][lane] * gW3[lane] + h2[r][lane + 32] * gW3[lane + 32];
        #pragma unroll
        for (int o = 16; o >= 1; o >>= 1) a += __shfl_xor_sync(0xffffffffu, a, o);
        if (lane == 0) gsc[r] = 1.f / (1.f + expf(-(a + gb3[0])));
    }
    __syncthreads();

    if (tid < 64) {
        float acc[8];
        float bvv = cb1[tid];
        #pragma unroll
        for (int r = 0; r < 8; r++) acc[r] = bvv;
        for (int e = 0; e < EMB; e++) {
            float w = cW1[e * 64 + tid];
            #pragma unroll
            for (int r = 0; r < 8; r++) acc[r] = fmaf(xs[r][e], w, acc[r]);
        }
        #pragma unroll
        for (int r = 0; r < 8; r++) h1c[r][tid] = acc[r];
    }
    __syncthreads();
    for (int r = wid * 2; r < wid * 2 + 2; r++) {
        float v0 = h1c[r][lane], v1 = h1c[r][lane + 32];
        float s = v0 + v1;
        float ss = v0 * v0 + v1 * v1;
        #pragma unroll
        for (int o = 16; o >= 1; o >>= 1) {
            s  += __shfl_xor_sync(0xffffffffu, s, o);
            ss += __shfl_xor_sync(0xffffffffu, ss, o);
        }
        if (lane == 0) {
            float mu = s / 64.f;
            stat[r][0] = mu;
            stat[r][1] = ss / 64.f - mu * mu;
        }
    }
    __syncthreads();
    if (tid < 64) {
        #pragma unroll
        for (int r = 0; r < 8; r++) {
            float mu = stat[r][0], var = stat[r][1];
            float v = (h1c[r][tid] - mu) * rsqrtf(var + 1e-5f) * cg[tid] + cbe[tid];
            h1c[r][tid] = fmaxf(v, 0.f);
        }
    }
    __syncthreads();
    {
        int j = tid & 31, rr = tid >> 5;
        for (int rp = 0; rp < 2; rp++) {
            int r = rp * 4 + rr;
            float a = cb2[j];
            for (int i = 0; i < 64; i++) a = fmaf(h1c[r][i], cW2[i * 32 + j], a);
            h2c[r][j] = fmaxf(a, 0.f);
        }
    }
    __syncthreads();
    for (int r = wid * 2; r < wid * 2 + 2; r++) {
        float a = h2c[r][lane] * cW3[lane];
        #pragma unroll
        for (int o = 16; o >= 1; o >>= 1) a += __shfl_xor_sync(0xffffffffu, a, o);
        if (lane == 0) csc[r] = 1.f / (1.f + expf(-(a + cb3[0])));
    }
    __syncthreads();

    if (tid < 8) {
        int srow = (row0 + tid) & (SEQ - 1);
        float pos = 0.8f + 0.4f * (float)srow / 1023.f;
        float score = (0.7f * gsc[tid] + 0.3f * csc[tid]) * pos;
        int T = (int)ceilf(score * 20.f);
        T = min(max(T, 1), TMAXS);
        g_T[row0 + tid] = T;
    }
}

// ===========================================================================
// fp32x2-pumped GEMM core: BM=128, BN=64, BK=16, double-buffered.
// Bit-identical fp32 results (each f32x2 lane is an IEEE fp32 FMA, same
// k-order as the scalar FFMA core). Accumulators packed along m (pairs of
// adjacent rows); B values duplicated into both lanes.
// accp[p][j]: p=0 -> rows ty*4+{0,1}; p=1 -> ty*4+{2,3};
//             p=2 -> 64+ty*4+{0,1};   p=3 -> 64+ty*4+{2,3}; col tx*4+j.
// ===========================================================================
#define GM_PAD 132

__device__ __forceinline__ void gemm_core_f2(
    const float* __restrict__ Aptr,   // &A[bm][0], row stride EMB
    const float* __restrict__ Bptr,   // &W[0][bn]
    float As[2][16 * GM_PAD], float Bs[2][16 * 64],
    uint64_t accp[4][4], int t)
{
    const int tx = t & 15, ty = t >> 4;
    const int am = t >> 1, ak = (t & 1) * 8;
    const int bk = t >> 4, bn4 = (t & 15) * 4;

    const float* Ag = Aptr + (size_t)am * EMB + ak;
    const float* Bg = Bptr + (size_t)bk * EMB + bn4;

    float4 a0 = *(const float4*)(Ag);
    float4 a1 = *(const float4*)(Ag + 4);
    float4 b0 = *(const float4*)(Bg);

    As[0][(ak + 0) * GM_PAD + am] = a0.x;
    As[0][(ak + 1) * GM_PAD + am] = a0.y;
    As[0][(ak + 2) * GM_PAD + am] = a0.z;
    As[0][(ak + 3) * GM_PAD + am] = a0.w;
    As[0][(ak + 4) * GM_PAD + am] = a1.x;
    As[0][(ak + 5) * GM_PAD + am] = a1.y;
    As[0][(ak + 6) * GM_PAD + am] = a1.z;
    As[0][(ak + 7) * GM_PAD + am] = a1.w;
    *(float4*)&Bs[0][bk * 64 + bn4] = b0;
    __syncthreads();

    #pragma unroll 1
    for (int kt = 0; kt < EMB / 16; kt++) {
        const int cur = kt & 1, nxt = cur ^ 1;
        if (kt < EMB / 16 - 1) {
            a0 = *(const float4*)(Ag + (kt + 1) * 16);
            a1 = *(const float4*)(Ag + (kt + 1) * 16 + 4);
            b0 = *(const float4*)(Bg + (size_t)(kt + 1) * 16 * EMB);
        }
        #pragma unroll
        for (int k = 0; k < 16; k++) {
            uint64_t ap[4];
            ap[0] = *(const uint64_t*)&As[cur][k * GM_PAD + ty * 4];
            ap[1] = *(const uint64_t*)&As[cur][k * GM_PAD + ty * 4 + 2];
            ap[2] = *(const uint64_t*)&As[cur][k * GM_PAD + 64 + ty * 4];
            ap[3] = *(const uint64_t*)&As[cur][k * GM_PAD + 64 + ty * 4 + 2];
            float bf[4];
            *(float4*)(bf) = *(const float4*)&Bs[cur][k * 64 + tx * 4];
            uint64_t bd0 = dup2(bf[0]), bd1 = dup2(bf[1]);
            uint64_t bd2 = dup2(bf[2]), bd3 = dup2(bf[3]);
            #pragma unroll
            for (int p = 0; p < 4; p++) {
                fma2(accp[p][0], ap[p], bd0);
                fma2(accp[p][1], ap[p], bd1);
                fma2(accp[p][2], ap[p], bd2);
                fma2(accp[p][3], ap[p], bd3);
            }
        }
        if (kt < EMB / 16 - 1) {
            As[nxt][(ak + 0) * GM_PAD + am] = a0.x;
            As[nxt][(ak + 1) * GM_PAD + am] = a0.y;
            As[nxt][(ak + 2) * GM_PAD + am] = a0.z;
            As[nxt][(ak + 3) * GM_PAD + am] = a0.w;
            As[nxt][(ak + 4) * GM_PAD + am] = a1.x;
            As[nxt][(ak + 5) * GM_PAD + am] = a1.y;
            As[nxt][(ak + 6) * GM_PAD + am] = a1.z;
            As[nxt][(ak + 7) * GM_PAD + am] = a1.w;
            *(float4*)&Bs[nxt][bk * 64 + bn4] = b0;
        }
        __syncthreads();
    }
}

// ===========================================================================
// Kernel B: QKV (fp32x2 GEMM, bit-identical to fp32) + LIF spike-sum
// epilogue -> bf16 spike counts. V stores RAW counts (no /20).
// ===========================================================================
__global__ __launch_bounds__(256, 2) void qkv_kernel(
    const float* __restrict__ x,
    const float* __restrict__ Wq, const float* __restrict__ Wk, const float* __restrict__ Wv,
    const float* __restrict__ aq, const float* __restrict__ bq,
    const float* __restrict__ ak_, const float* __restrict__ bk_,
    const float* __restrict__ av, const float* __restrict__ bv)
{
    __shared__ float As[2][16 * GM_PAD];
    __shared__ float Bs[2][16 * 64];

    const int z = blockIdx.z;
    const float* W = (z == 0) ? Wq : ((z == 1) ? Wk : Wv);
    __nv_bfloat16* out = (z == 0) ? g_qb : ((z == 1) ? g_kb : g_vb);
    const float alpha = ((z == 0) ? aq : ((z == 1) ? ak_ : av))[0];
    const float beta  = ((z == 0) ? bq : ((z == 1) ? bk_ : bv))[0];

    const int t = threadIdx.x;
    const int tx = t & 15, ty = t >> 4;
    const int bm = blockIdx.y * 128, bn = blockIdx.x * 64;

    uint64_t accp[4][4];
    #pragma unroll
    for (int p = 0; p < 4; p++)
        #pragma unroll
        for (int j = 0; j < 4; j++) accp[p][j] = 0ull;

    gemm_core_f2(x + (size_t)bm * EMB, W + bn, As, Bs, accp, t);

    // unpack pairs, run LIF per row
    #pragma unroll
    for (int p = 0; p < 4; p++) {
        #pragma unroll
        for (int half = 0; half < 2; half++) {
            // p<2 -> rows ty*4 + p*2 + half; p>=2 -> 64 + ty*4 + (p-2)*2 + half
            const int mloc = (p < 2) ? (ty * 4 + p * 2 + half)
                                     : (64 + ty * 4 + (p - 2) * 2 + half);
            const int r = bm + mloc;
            const int T = g_T[r];
            float y[4];
            #pragma unroll
            for (int j = 0; j < 4; j++) {
                float lo, hi;
                unpack2(accp[p][j], lo, hi);
                y[j] = half ? hi : lo;
            }
            float iv[4], vv[4], sa[4];
            #pragma unroll
            for (int j = 0; j < 4; j++) { iv[j] = 0.f; vv[j] = 0.f; sa[j] = 0.f; }
            for (int tt = 0; tt < T; tt++) {
                #pragma unroll
                for (int j = 0; j < 4; j++) {
                    iv[j] = fmaf(alpha, iv[j], y[j]);
                    vv[j] = fmaf(beta, vv[j], iv[j]);
                    float sp = (vv[j] >= 1.f) ? 1.f : 0.f;
                    sa[j] += sp;
                    vv[j] *= (1.f - sp);
                }
            }
            __nv_bfloat162* o2 = (__nv_bfloat162*)(out + (size_t)r * EMB + bn + tx * 4);
            o2[0] = __nv_bfloat162(__float2bfloat16(sa[0]), __float2bfloat16(sa[1]));
            o2[1] = __nv_bfloat162(__float2bfloat16(sa[2]), __float2bfloat16(sa[3]));
        }
    }
}

// ===========================================================================
// Kernel C: flash attention with warp-level bf16 MMA (unchanged from R6).
// ===========================================================================
#define KVPAD 72

__global__ __launch_bounds__(256) void attn_kernel()
{
    __shared__ __nv_bfloat16 sK[2][64 * KVPAD];
    __shared__ __nv_bfloat16 sV[2][64 * KVPAD];

    const int t = threadIdx.x;
    const int w = t >> 5, lane = t & 31;
    const int g = lane >> 2, tg = lane & 3;
    const int b = blockIdx.z, h = blockIdx.y;
    const int q0 = blockIdx.x * 128;
    const int qrow = q0 + w * 16;

    uint32_t qa[4][4];
    {
        const __nv_bfloat16* Qg = g_qb + (size_t)(b * SEQ + qrow) * EMB + h * HD;
        #pragma unroll
        for (int kt = 0; kt < 4; kt++) {
            qa[kt][0] = *(const uint32_t*)(Qg + (size_t)g * EMB + kt * 16 + 2 * tg);
            qa[kt][1] = *(const uint32_t*)(Qg + (size_t)(g + 8) * EMB + kt * 16 + 2 * tg);
            qa[kt][2] = *(const uint32_t*)(Qg + (size_t)g * EMB + kt * 16 + 8 + 2 * tg);
            qa[kt][3] = *(const uint32_t*)(Qg + (size_t)(g + 8) * EMB + kt * 16 + 8 + 2 * tg);
        }
    }

    const uint32_t kRowOff = (uint32_t)(lane & 7) * KVPAD + ((lane >> 3) & 1) * 8;
    const uint32_t vRowOff = (uint32_t)(lane & 15) * KVPAD;

    const __nv_bfloat16* Kg = g_kb + (size_t)(b * SEQ) * EMB + h * HD;
    const __nv_bfloat16* Vg = g_vb + (size_t)(b * SEQ) * EMB + h * HD;
    const int ldrow = t >> 2, ldsg = t & 3;

    {
        const __nv_bfloat16* kg = Kg + (size_t)ldrow * EMB;
        const __nv_bfloat16* vg = Vg + (size_t)ldrow * EMB;
        uint32_t ks = smem_u32(&sK[0][ldrow * KVPAD]);
        uint32_t vs = smem_u32(&sV[0][ldrow * KVPAD]);
        CP_ASYNC16(ks + ldsg * 16, kg + ldsg * 8);
        CP_ASYNC16(ks + (ldsg + 4) * 16, kg + (ldsg + 4) * 8);
        CP_ASYNC16(vs + ldsg * 16, vg + ldsg * 8);
        CP_ASYNC16(vs + (ldsg + 4) * 16, vg + (ldsg + 4) * 8);
        CP_COMMIT();
    }

    float o[8][4];
    #pragma unroll
    for (int nt = 0; nt < 8; nt++)
        #pragma unroll
        for (int i = 0; i < 4; i++) o[nt][i] = 0.f;
    float mA = -1e30f, mB = -1e30f, lA = 0.f, lB = 0.f;

    #pragma unroll 1
    for (int j = 0; j < 16; j++) {
        const int buf = j & 1;

        if (j < 15) {
            const int j1 = (j + 1) * 64;
            const __nv_bfloat16* kg = Kg + (size_t)(j1 + ldrow) * EMB;
            const __nv_bfloat16* vg = Vg + (size_t)(j1 + ldrow) * EMB;
            uint32_t ks = smem_u32(&sK[buf ^ 1][ldrow * KVPAD]);
            uint32_t vs = smem_u32(&sV[buf ^ 1][ldrow * KVPAD]);
            CP_ASYNC16(ks + ldsg * 16, kg + ldsg * 8);
            CP_ASYNC16(ks + (ldsg + 4) * 16, kg + (ldsg + 4) * 8);
            CP_ASYNC16(vs + ldsg * 16, vg + ldsg * 8);
            CP_ASYNC16(vs + (ldsg + 4) * 16, vg + (ldsg + 4) * 8);
            CP_COMMIT();
            CP_WAIT(1);
        } else {
            CP_WAIT(0);
        }
        __syncthreads();

        float s[8][4];
        const uint32_t kb = smem_u32(&sK[buf][0]);
        #pragma unroll
        for (int nt = 0; nt < 8; nt++) {
            #pragma unroll
            for (int i = 0; i < 4; i++) s[nt][i] = 0.f;
            #pragma unroll
            for (int kt = 0; kt < 4; kt++) {
                uint32_t k0, k1;
                LDMATRIX_X2(k0, k1, kb + (uint32_t)(nt * 8 * KVPAD + kt * 16) * 2 + kRowOff * 2);
                MMA_BF16(s[nt], qa[kt], k0, k1);
            }
        }

        float mxA = -1e30f, mxB = -1e30f;
        #pragma unroll
        for (int nt = 0; nt < 8; nt++) {
            s[nt][0] *= 0.125f; s[nt][1] *= 0.125f;
            s[nt][2] *= 0.125f; s[nt][3] *= 0.125f;
            mxA = fmaxf(mxA, fmaxf(s[nt][0], s[nt][1]));
            mxB = fmaxf(mxB, fmaxf(s[nt][2], s[nt][3]));
        }
        mxA = fmaxf(mxA, __shfl_xor_sync(0xffffffffu, mxA, 1));
        mxA = fmaxf(mxA, __shfl_xor_sync(0xffffffffu, mxA, 2));
        mxB = fmaxf(mxB, __shfl_xor_sync(0xffffffffu, mxB, 1));
        mxB = fmaxf(mxB, __shfl_xor_sync(0xffffffffu, mxB, 2));

        const float mnA = fmaxf(mA, mxA), mnB = fmaxf(mB, mxB);
        const float facA = __expf(mA - mnA), facB = __expf(mB - mnB);
        mA = mnA; mB = mnB;

        float sumA = 0.f, sumB = 0.f;
        #pragma unroll
        for (int nt = 0; nt < 8; nt++) {
            s[nt][0] = __expf(s[nt][0] - mnA);
            s[nt][1] = __expf(s[nt][1] - mnA);
            s[nt][2] = __expf(s[nt][2] - mnB);
            s[nt][3] = __expf(s[nt][3] - mnB);
            sumA += s[nt][0] + s[nt][1];
            sumB += s[nt][2] + s[nt][3];
        }
        sumA += __shfl_xor_sync(0xffffffffu, sumA, 1);
        sumA += __shfl_xor_sync(0xffffffffu, sumA, 2);
        sumB += __shfl_xor_sync(0xffffffffu, sumB, 1);
        sumB += __shfl_xor_sync(0xffffffffu, sumB, 2);
        lA = lA * facA + sumA;
        lB = lB * facB + sumB;

        #pragma unroll
        for (int nt = 0; nt < 8; nt++) {
            o[nt][0] *= facA; o[nt][1] *= facA;
            o[nt][2] *= facB; o[nt][3] *= facB;
        }

        uint32_t phi[4][4], plo[4][4];
        #pragma unroll
        for (int kt2 = 0; kt2 < 4; kt2++) {
            const int n0 = 2 * kt2, n1 = 2 * kt2 + 1;
            float p00 = s[n0][0], p01 = s[n0][1], p02 = s[n0][2], p03 = s[n0][3];
            float p10 = s[n1][0], p11 = s[n1][1], p12 = s[n1][2], p13 = s[n1][3];
            uint32_t h00 = pack_bf2(p00, p01), h01 = pack_bf2(p02, p03);
            uint32_t h10 = pack_bf2(p10, p11), h11 = pack_bf2(p12, p13);
            phi[kt2][0] = h00; phi[kt2][1] = h01; phi[kt2][2] = h10; phi[kt2][3] = h11;
            __nv_bfloat162 b00 = *(__nv_bfloat162*)&h00, b01 = *(__nv_bfloat162*)&h01;
            __nv_bfloat162 b10 = *(__nv_bfloat162*)&h10, b11 = *(__nv_bfloat162*)&h11;
            plo[kt2][0] = pack_bf2(p00 - __bfloat162float(b00.x), p01 - __bfloat162float(b00.y));
            plo[kt2][1] = pack_bf2(p02 - __bfloat162float(b01.x), p03 - __bfloat162float(b01.y));
            plo[kt2][2] = pack_bf2(p10 - __bfloat162float(b10.x), p11 - __bfloat162float(b10.y));
            plo[kt2][3] = pack_bf2(p12 - __bfloat162float(b11.x), p13 - __bfloat162float(b11.y));
        }

        const uint32_t vb = smem_u32(&sV[buf][0]);
        #pragma unroll
        for (int kt2 = 0; kt2 < 4; kt2++) {
            #pragma unroll
            for (int nt = 0; nt < 8; nt++) {
                uint32_t v0, v1;
                LDMATRIX_X2_T(v0, v1, vb + (uint32_t)(kt2 * 16 * KVPAD + nt * 8) * 2 + vRowOff * 2);
                MMA_BF16(o[nt], phi[kt2], v0, v1);
                MMA_BF16(o[nt], plo[kt2], v0, v1);
            }
        }
        __syncthreads();
    }

    {
        const float invA = 1.f / (lA * 20.f), invB = 1.f / (lB * 20.f);
        float* OgA = g_attn + (size_t)(b * SEQ + qrow + g) * EMB + h * HD;
        float* OgB = g_attn + (size_t)(b * SEQ + qrow + g + 8) * EMB + h * HD;
        #pragma unroll
        for (int nt = 0; nt < 8; nt++) {
            *(float2*)(OgA + nt * 8 + 2 * tg) = make_float2(o[nt][0] * invA, o[nt][1] * invA);
            *(float2*)(OgB + nt * 8 + 2 * tg) = make_float2(o[nt][2] * invB, o[nt][3] * invB);
        }
    }
}

// ===========================================================================
// 3xTF32 tensor-core GEMM core (proj only; no threshold downstream).
// BM=128, BN=64, BK=16; 8 warps 4x2; warp tile 32x32; err ~1e-6.
// ===========================================================================
#define APAD 136
#define BPAD 72

__device__ __forceinline__ void tf32_core(
    const float* __restrict__ Aptr,
    const float* __restrict__ Bptr,
    float As[2][16 * APAD], float Bs[2][16 * BPAD],
    float c[2][4][4], int t)
{
    const int am = t >> 1, ak = (t & 1) * 8;
    const int bk = t >> 4, bn4 = (t & 15) * 4;
    const int w = t >> 5, lane = t & 31;
    const int wm = (w & 3) * 32, wn = (w >> 2) * 32;
    const int g = lane >> 2, tg = lane & 3;

    const float* Ag = Aptr + (size_t)am * EMB + ak;
    const float* Bg = Bptr + (size_t)bk * EMB + bn4;

    float4 a0 = *(const float4*)(Ag);
    float4 a1 = *(const float4*)(Ag + 4);
    float4 b0 = *(const float4*)(Bg);

    As[0][(ak + 0) * APAD + am] = a0.x;
    As[0][(ak + 1) * APAD + am] = a0.y;
    As[0][(ak + 2) * APAD + am] = a0.z;
    As[0][(ak + 3) * APAD + am] = a0.w;
    As[0][(ak + 4) * APAD + am] = a1.x;
    As[0][(ak + 5) * APAD + am] = a1.y;
    As[0][(ak + 6) * APAD + am] = a1.z;
    As[0][(ak + 7) * APAD + am] = a1.w;
    *(float4*)&Bs[0][bk * BPAD + bn4] = b0;
    __syncthreads();

    #pragma unroll 1
    for (int kt = 0; kt < EMB / 16; kt++) {
        const int cur = kt & 1, nxt = cur ^ 1;
        if (kt < EMB / 16 - 1) {
            a0 = *(const float4*)(Ag + (kt + 1) * 16);
            a1 = *(const float4*)(Ag + (kt + 1) * 16 + 4);
            b0 = *(const float4*)(Bg + (size_t)(kt + 1) * 16 * EMB);
        }
        #pragma unroll
        for (int ks = 0; ks < 16; ks += 8) {
            uint32_t ahi[2][4], alo[2][4];
            #pragma unroll
            for (int mi = 0; mi < 2; mi++) {
                const int m = wm + mi * 16 + g;
                float f0 = As[cur][(ks + tg) * APAD + m];
                float f1 = As[cur][(ks + tg) * APAD + m + 8];
                float f2 = As[cur][(ks + tg + 4) * APAD + m];
                float f3 = As[cur][(ks + tg + 4) * APAD + m + 8];
                split_tf32(f0, ahi[mi][0], alo[mi][0]);
                split_tf32(f1, ahi[mi][1], alo[mi][1]);
                split_tf32(f2, ahi[mi][2], alo[mi][2]);
                split_tf32(f3, ahi[mi][3], alo[mi][3]);
            }
            uint32_t bhi[4][2], blo[4][2];
            #pragma unroll
            for (int ni = 0; ni < 4; ni++) {
                const int n = wn + ni * 8 + g;
                float f0 = Bs[cur][(ks + tg) * BPAD + n];
                float f1 = Bs[cur][(ks + tg + 4) * BPAD + n];
                split_tf32(f0, bhi[ni][0], blo[ni][0]);
                split_tf32(f1, bhi[ni][1], blo[ni][1]);
            }
            #pragma unroll
            for (int mi = 0; mi < 2; mi++)
                #pragma unroll
                for (int ni = 0; ni < 4; ni++) {
                    MMA_TF32(c[mi][ni], ahi[mi], bhi[ni][0], bhi[ni][1]);
                    MMA_TF32(c[mi][ni], ahi[mi], blo[ni][0], blo[ni][1]);
                    MMA_TF32(c[mi][ni], alo[mi], bhi[ni][0], bhi[ni][1]);
                }
        }
        if (kt < EMB / 16 - 1) {
            As[nxt][(ak + 0) * APAD + am] = a0.x;
            As[nxt][(ak + 1) * APAD + am] = a0.y;
            As[nxt][(ak + 2) * APAD + am] = a0.z;
            As[nxt][(ak + 3) * APAD + am] = a0.w;
            As[nxt][(ak + 4) * APAD + am] = a1.x;
            As[nxt][(ak + 5) * APAD + am] = a1.y;
            As[nxt][(ak + 6) * APAD + am] = a1.z;
            As[nxt][(ak + 7) * APAD + am] = a1.w;
            *(float4*)&Bs[nxt][bk * BPAD + bn4] = b0;
        }
        __syncthreads();
    }
}

// ===========================================================================
// Kernel D: output projection (3xTF32)  out = g_attn @ Wo + bo
// ===========================================================================
__global__ __launch_bounds__(256, 2) void proj_kernel(
    const float* __restrict__ Wo, const float* __restrict__ bo, float* __restrict__ out)
{
    __shared__ float As[2][16 * APAD];
    __shared__ float Bs[2][16 * BPAD];

    const int t = threadIdx.x;
    const int w = t >> 5, lane = t & 31;
    const int wm = (w & 3) * 32, wn = (w >> 2) * 32;
    const int g = lane >> 2, tg = lane & 3;
    const int bm = blockIdx.y * 128, bn = blockIdx.x * 64;

    float c[2][4][4];
    #pragma unroll
    for (int mi = 0; mi < 2; mi++)
        #pragma unroll
        for (int ni = 0; ni < 4; ni++)
            #pragma unroll
            for (int i = 0; i < 4; i++) c[mi][ni][i] = 0.f;

    tf32_core(g_attn + (size_t)bm * EMB, Wo + bn, As, Bs, c, t);

    #pragma unroll
    for (int ni = 0; ni < 4; ni++) {
        const int cn = bn + wn + ni * 8 + tg * 2;
        const float b0v = bo[cn], b1v = bo[cn + 1];
        #pragma unroll
        for (int mi = 0; mi < 2; mi++) {
            const int r0 = bm + wm + mi * 16 + g;
            *(float2*)(out + (size_t)r0 * EMB + cn) =
                make_float2(c[mi][ni][0] + b0v, c[mi][ni][1] + b1v);
            *(float2*)(out + (size_t)(r0 + 8) * EMB + cn) =
                make_float2(c[mi][ni][2] + b0v, c[mi][ni][3] + b1v);
        }
    }
}

// ===========================================================================
extern "C" void kernel_launch(void* const* d_in, const int* in_sizes, int n_in,
                              void* d_out, int out_size)
{
    (void)in_sizes; (void)n_in; (void)out_size;
    const float* x   = (const float*)d_in[0];
    const float* Wq  = (const float*)d_in[1];
    const float* Wk  = (const float*)d_in[2];
    const float* Wv  = (const float*)d_in[3];
    const float* Wo  = (const float*)d_in[4];
    const float* bo  = (const float*)d_in[5];
    const float* gW1 = (const float*)d_in[6];
    const float* gb1 = (const float*)d_in[7];
    const float* gg  = (const float*)d_in[8];
    const float* gbe = (const float*)d_in[9];
    const float* gW2 = (const float*)d_in[10];
    const float* gb2 = (const float*)d_in[11];
    const float* gW3 = (const float*)d_in[12];
    const float* gb3 = (const float*)d_in[13];
    const float* cW1 = (const float*)d_in[14];
    const float* cb1 = (const float*)d_in[15];
    const float* cg  = (const float*)d_in[16];
    const float* cbe = (const float*)d_in[17];
    const float* cW2 = (const float*)d_in[18];
    const float* cb2 = (const float*)d_in[19];
    const float* cW3 = (const float*)d_in[20];
    const float* cb3 = (const float*)d_in[21];
    const float* aq  = (const float*)d_in[22];
    const float* bq  = (const float*)d_in[23];
    const float* ak  = (const float*)d_in[24];
    const float* bk  = (const float*)d_in[25];
    const float* av  = (const float*)d_in[26];
    const float* bv  = (const float*)d_in[27];
    float* out = (float*)d_out;

    gate_kernel<<<MROWS / 8, 128>>>(x, gW1, gb1, gg, gbe, gW2, gb2, gW3, gb3,
                                    cW1, cb1, cg, cbe, cW2, cb2, cW3, cb3);

    qkv_kernel<<<dim3(EMB / 64, MROWS / 128, 3), 256>>>(x, Wq, Wk, Wv,
                                                        aq, bq, ak, bk, av, bv);

    attn_kernel<<<dim3(SEQ / 128, NH, BCNT), 256>>>();

    proj_kernel<<<dim3(EMB / 64, MROWS / 128), 256>>>(Wo, bo, out);
}